// round 4
// baseline (speedup 1.0000x reference)
#include <cuda_runtime.h>
#include <math.h>

#define NB 4096
#define NC 128
#define KC 32
#define ED 128
#define MATSZ 16777216ULL   // 4096*4096

__device__ float d_partial[NC];
__device__ unsigned d_ticket;   // zero-init; last block resets

typedef unsigned long long u64;

__device__ __forceinline__ u64 fma2(u64 a, u64 b, u64 c) {
    u64 d;
    asm("fma.rn.f32x2 %0, %1, %2, %3;" : "=l"(d) : "l"(a), "l"(b), "l"(c));
    return d;
}
#define PK2(v, lo, hi)   asm("mov.b64 %0, {%1, %2};" : "=l"(v) : "f"(lo), "f"(hi))
#define UNPK2(lo, hi, v) asm("mov.b64 {%0, %1}, %2;" : "=f"(lo), "=f"(hi) : "l"(v))

// ---- dynamic smem word offsets -------------------------------------------
#define A_W    0        // 8192 w: emb-dup (prologue) -> w2p u64[4096] (main)
#define B_W    8192     // 8192 w: w1 staging / psw1T (prologue) -> h1p u64[2048] + s_part
#define SPART  12288    // 256 w (inside B after h1p's 4096 w)
#define HIT    16384    // 4224 w  hiT[k*33 + i]
#define HJT    20608    // 4224 w  hjT[k*33 + j]
#define DISTW  24832    // 1024
#define EFFW   25856    // 1024
#define PFW    26880    // 1024
#define FLOWW  27904    // 1024
#define CVW    28928    // 128  (hour_f*w1h + b1)
#define W1DW   29056    // 128
#define GIDX   29184    // int[32]
#define NETW   29216
#define PRIOW  29248
#define ORDW   29280    // int[32]
#define ACTBW  29312    // unsigned[32]
#define DNETW  29344
#define NSRTW  29376
#define RSENTW 29408
#define WCNTW  29440    // int[8]
#define POSW   29448    // float2[32] = 64 w
#define SM_WORDS 29520
#define SM_BYTES (SM_WORDS * 4)

__global__ void __launch_bounds__(256, 1) mega_kernel(
    const float* __restrict__ emb,  const float* __restrict__ gen,
    const float* __restrict__ cons, const float* __restrict__ pos,
    const float* __restrict__ fpw1, const float* __restrict__ fpb1,
    const float* __restrict__ fpw2, const float* __restrict__ fpb2,
    const float* __restrict__ fpw3, const float* __restrict__ fpb3,
    const float* __restrict__ enw1, const float* __restrict__ enb1,
    const float* __restrict__ enw2, const float* __restrict__ enb2,
    const float* __restrict__ psw1, const float* __restrict__ psb1,
    const float* __restrict__ psw2, const float* __restrict__ psb2,
    const int* __restrict__ assign, const int* __restrict__ hour_p,
    float* __restrict__ out) {
    extern __shared__ float smf[];
    int* s_gidx = (int*)(smf + GIDX);
    int* s_ord  = (int*)(smf + ORDW);
    unsigned* s_actb = (unsigned*)(smf + ACTBW);
    int* s_wcnt = (int*)(smf + WCNTW);
    float2* s_pos2 = (float2*)(smf + POSW);
    float* s_part = smf + SPART;

    const int c = blockIdx.x;
    const int t = threadIdx.x;
    const int w = t >> 5, lane = t & 31;
    const int hour = hour_p ? *hour_p : 12;

    // ================= A. stable grouping (2-pass ballot) ==================
    {
        int a[16];
        const int* ap = assign + w * 512;
#pragma unroll
        for (int q = 0; q < 16; q++) a[q] = ap[q * 32 + lane];
        unsigned balls[16];
        int cnt = 0;
#pragma unroll
        for (int q = 0; q < 16; q++) {
            balls[q] = __ballot_sync(0xffffffffu, a[q] == c);
            cnt += __popc(balls[q]);
        }
        if (lane == 0) s_wcnt[w] = cnt;
        __syncthreads();
        int run = 0;
        for (int ww = 0; ww < 8; ww++) if (ww < w) run += s_wcnt[ww];
#pragma unroll
        for (int q = 0; q < 16; q++) {
            if (a[q] == c) {
                int p = run + __popc(balls[q] & ((1u << lane) - 1u));
                if (p < KC) s_gidx[p] = w * 512 + q * 32 + lane;
            }
            run += __popc(balls[q]);
        }
    }
    __syncthreads();

    // ================= B. net, positions, emb-dup, cv/w1d ==================
    if (t < KC) {
        int b = s_gidx[t];
        smf[NETW + t] = gen[b * 24 + hour] - cons[b * 24 + hour];
        s_pos2[t] = make_float2(pos[b * 2], pos[b * 2 + 1]);
    }
    {
        float hour_f = (float)hour * (1.f / 24.f);
        if (t < 128) {
            smf[W1DW + t] = fpw1[(size_t)t * 258 + 256];
            smf[CVW + t] = fmaf(hour_f, fpw1[(size_t)t * 258 + 257], fpb1[t]);
        }
        float2* embd = (float2*)(smf + A_W);
        for (int i = t; i < KC * ED; i += 256) {
            int r = i >> 7, e = i & 127;
            float v = emb[(size_t)s_gidx[r] * ED + e];
            embd[r * 128 + e] = make_float2(v, v);
        }
    }

    // ================= C. hij GEMM -> hiT/hjT transposed ===================
    {
        float* s_w1c = smf + B_W;     // [kk][col] stride 256
        const u64* embU = (const u64*)(smf + A_W);
        int p = t & 127, rh = t >> 7;
        u64 acc[16];
#pragma unroll
        for (int r = 0; r < 16; r++) acc[r] = 0ull;
        for (int kc = 0; kc < 4; kc++) {
            __syncthreads();
            for (int i = t; i < 8192; i += 256) {
                int col = i >> 5, kk = i & 31;
                float v = (col < 128)
                    ? fpw1[(size_t)col * 258 + kc * 32 + kk]
                    : fpw1[(size_t)(col - 128) * 258 + 128 + kc * 32 + kk];
                s_w1c[kk * 256 + col] = v;
            }
            __syncthreads();
            for (int kk = 0; kk < 32; kk++) {
                u64 wp = *(const u64*)(s_w1c + kk * 256 + 2 * p);
                const u64* eb = embU + (rh * 16) * 128 + kc * 32 + kk;
#pragma unroll
                for (int r = 0; r < 16; r++)
                    acc[r] = fma2(eb[r * 128], wp, acc[r]);
            }
        }
        int base = (p < 64) ? HIT : HJT;
        int c0 = (p < 64) ? 2 * p : 2 * p - 128;
#pragma unroll
        for (int r = 0; r < 16; r++) {
            float lo, hi;
            UNPK2(lo, hi, acc[r]);
            int row = rh * 16 + r;
            smf[base + c0 * 33 + row] = lo;
            smf[base + (c0 + 1) * 33 + row] = hi;
        }
    }
    __syncthreads();

    // ================= D. priority MLP =====================================
    {
        float* s_pT = smf + B_W;      // psw1T [e*33+m]
        for (int i = t; i < 4096; i += 256) {
            int m = i >> 7, e = i & 127;
            s_pT[e * 33 + m] = psw1[i];
        }
        __syncthreads();
        const float* embF = smf + A_W;   // dup: scalar at idx*2
        float b1m = psb1[lane], w2m = psw2[lane], b2s = psb2[0];
#pragma unroll
        for (int rr = 0; rr < 4; rr++) {
            int r = w * 4 + rr;
            float acc = b1m;
#pragma unroll 8
            for (int e = 0; e < 128; e++)
                acc = fmaf(embF[(r * 128 + e) * 2], s_pT[e * 33 + lane], acc);
            float v = fmaxf(acc, 0.f) * w2m;
#pragma unroll
            for (int o = 16; o > 0; o >>= 1) v += __shfl_xor_sync(0xffffffffu, v, o);
            if (lane == 0) smf[PRIOW + r] = 1.f / (1.f + expf(-(v + b2s)));
        }
    }

    // ================= E. dist + efficiency ================================
    {
        float b2v = enb2[0];
        for (int pp = t; pp < 1024; pp += 256) {
            int i = pp >> 5, j = pp & 31;
            float2 pi = s_pos2[i], pj = s_pos2[j];
            float dx = pi.x - pj.x, dy = pi.y - pj.y;
            float dist = sqrtf(dx * dx + dy * dy);
            float tq = dist * (1.f / 1000.f);
            float s = 0.f;
#pragma unroll
            for (int l = 0; l < 16; l++)
                s = fmaf(fmaxf(fmaf(tq, __ldg(enw1 + l), __ldg(enb1 + l)), 0.f),
                         __ldg(enw2 + l), s);
            smf[EFFW + pp] = 0.85f + 0.13f / (1.f + expf(-(s + b2v)));
            smf[DISTW + pp] = dist;
        }
    }
    __syncthreads();

    // ================= F. stage w2p (k-pair packed) ========================
    {
        float2* w2p = (float2*)(smf + A_W);   // slot kp*64 + n
        for (int idx = t; idx < 4096; idx += 256) {
            int kp = idx & 63, n = idx >> 6;
            w2p[kp * 64 + n] = *(const float2*)(fpw2 + n * 128 + 2 * kp);
        }
    }

    // consumer constants
    const int jp = lane & 15;         // j0 = jp, j1 = jp + 16
    const int nh = lane >> 4;
    const int nb = w * 8 + nh * 4;    // 4 n values
    float4 w3q = *(const float4*)(fpw3 + nb);
    u64 b2p0, b2p1, b2p2, b2p3;
    {
        float4 b2q = *(const float4*)(fpb2 + nb);
        PK2(b2p0, b2q.x, 0.f); PK2(b2p1, b2q.y, 0.f);
        PK2(b2p2, b2q.z, 0.f); PK2(b2p3, b2q.w, 0.f);
    }
    float b3 = fpb3[0];
    __syncthreads();

    // ================= G. mainloop over senders i ==========================
    {
        float* h1pf = smf + B_W;                  // h1p as floats
        const u64* h1u = (const u64*)(smf + B_W);
        const u64* w2u = (const u64*)(smf + A_W);
        const float4 z4 = make_float4(0.f, 0.f, 0.f, 0.f);
        const float4 o4 = make_float4(1.f, 1.f, 1.f, 1.f);
        float4* outS4 = (float4*)out;
        float4* outE4 = (float4*)(out + MATSZ);

        for (int i = 0; i < 32; i++) {
            // ---- deferred pf reduce for i-1 -------------------------------
            if (i > 0) {
                int jr = w * 4 + (lane >> 3);
                int sw = lane & 7;
                float v = s_part[sw * 32 + jr];
                v += __shfl_xor_sync(0xffffffffu, v, 1);
                v += __shfl_xor_sync(0xffffffffu, v, 2);
                v += __shfl_xor_sync(0xffffffffu, v, 4);
                if (sw == 0) {
                    float x = v + b3;
                    smf[PFW + (i - 1) * 32 + jr] = (x > 20.f) ? x : log1pf(expf(x));
                }
            }
            // ---- producer: warp w covers k in [w*16, w*16+16), lane = j ---
            {
                float dd = smf[DISTW + i * 32 + lane];
#pragma unroll
                for (int s = 0; s < 16; s++) {
                    int k = w * 16 + s;
                    float h = smf[HIT + k * 33 + i] + smf[HJT + k * 33 + lane]
                            + fmaf(dd, smf[W1DW + k], smf[CVW + k]);
                    h = fmaxf(h, 0.f);
                    h1pf[(k >> 1) * 64 + lane * 2 + (k & 1)] = h;
                }
            }
            // ---- fill this sender's output row (default values) -----------
            {
                size_t rb = (size_t)s_gidx[i] * 1024;
#pragma unroll
                for (int q = 0; q < 4; q++) {
                    outS4[rb + q * 256 + t] = z4;
                    outE4[rb + q * 256 + t] = o4;
                }
            }
            __syncthreads();

            // ---- consumer GEMM: k-pair packed FFMA2 -----------------------
            u64 a0 = b2p0, a1 = b2p1, a2 = b2p2, a3 = b2p3;   // j0, n0..n3
            u64 a4 = b2p0, a5 = b2p1, a6 = b2p2, a7 = b2p3;   // j1
#pragma unroll 8
            for (int kp = 0; kp < 64; kp++) {
                u64 h0 = h1u[kp * 32 + jp];
                u64 h1 = h1u[kp * 32 + jp + 16];
                ulonglong2 wva = *(const ulonglong2*)(w2u + kp * 64 + nb);
                ulonglong2 wvb = *(const ulonglong2*)(w2u + kp * 64 + nb + 2);
                a0 = fma2(h0, wva.x, a0);
                a1 = fma2(h0, wva.y, a1);
                a2 = fma2(h0, wvb.x, a2);
                a3 = fma2(h0, wvb.y, a3);
                a4 = fma2(h1, wva.x, a4);
                a5 = fma2(h1, wva.y, a5);
                a6 = fma2(h1, wvb.x, a6);
                a7 = fma2(h1, wvb.y, a7);
            }
            // ---- epilogue: h2=lo+hi, relu, dot w3, fold nh halves ---------
            float lo, hi, vj0, vj1;
            UNPK2(lo, hi, a0); vj0 = fmaxf(lo + hi, 0.f) * w3q.x;
            UNPK2(lo, hi, a1); vj0 = fmaf(fmaxf(lo + hi, 0.f), w3q.y, vj0);
            UNPK2(lo, hi, a2); vj0 = fmaf(fmaxf(lo + hi, 0.f), w3q.z, vj0);
            UNPK2(lo, hi, a3); vj0 = fmaf(fmaxf(lo + hi, 0.f), w3q.w, vj0);
            UNPK2(lo, hi, a4); vj1 = fmaxf(lo + hi, 0.f) * w3q.x;
            UNPK2(lo, hi, a5); vj1 = fmaf(fmaxf(lo + hi, 0.f), w3q.y, vj1);
            UNPK2(lo, hi, a6); vj1 = fmaf(fmaxf(lo + hi, 0.f), w3q.z, vj1);
            UNPK2(lo, hi, a7); vj1 = fmaf(fmaxf(lo + hi, 0.f), w3q.w, vj1);
            vj0 += __shfl_xor_sync(0xffffffffu, vj0, 16);
            vj1 += __shfl_xor_sync(0xffffffffu, vj1, 16);
            s_part[w * 32 + lane] = (lane < 16) ? vj0 : vj1;
            __syncthreads();
        }
        // final pf reduce for i = 31
        {
            int jr = w * 4 + (lane >> 3);
            int sw = lane & 7;
            float v = s_part[sw * 32 + jr];
            v += __shfl_xor_sync(0xffffffffu, v, 1);
            v += __shfl_xor_sync(0xffffffffu, v, 2);
            v += __shfl_xor_sync(0xffffffffu, v, 4);
            if (sw == 0) {
                float x = v + b3;
                smf[PFW + 31 * 32 + jr] = (x > 20.f) ? x : log1pf(expf(x));
            }
        }
    }
    __syncthreads();

    // ================= H. greedy (warp 0, prefix-scan water-filling) =======
    if (w == 0) {
        float pr = smf[PRIOW + lane];
        int r = 0;
#pragma unroll
        for (int l = 0; l < KC; l++) {
            float q = smf[PRIOW + l];
            r += (q > pr) || (q == pr && l < lane);
        }
        s_ord[r] = lane;
        __syncwarp();
        int oj = s_ord[lane];
        float nets = smf[NETW + oj];
        float dn = nets;
        for (int i = 0; i < 32; i++) {
            int oi = s_ord[i];
            float A = fmaxf(__shfl_sync(0xffffffffu, nets, i), 0.f);
            float needed = -dn;
            float pf = smf[PFW + oi * 32 + oj];
            float cap = (needed > 0.f) ? fminf(needed, pf) : 0.f;
            float C = cap;
#pragma unroll
            for (int o = 1; o < 32; o <<= 1) {
                float x = __shfl_up_sync(0xffffffffu, C, o);
                if (lane >= o) C += x;
            }
            float Cprev = C - cap;
            float avail = A - Cprev;
            bool act = (avail > 0.f) && (needed > 0.f);
            float f = act ? fminf(fminf(avail, needed), pf) : 0.f;
            dn += f * smf[EFFW + oi * 32 + oj];
            smf[FLOWW + i * 32 + lane] = f;
            unsigned ab = __ballot_sync(0xffffffffu, act);
            if (lane == 0) s_actb[i] = ab;
        }
        smf[DNETW + lane] = dn;
        smf[NSRTW + lane] = nets;
    }
    __syncthreads();

    // ================= I. scatter ==========================================
    {
        float* out_sh = out;
        float* out_ef = out + MATSZ;
        float* out_sent = out + 2 * MATSZ + 1;
        float* out_recv = out_sent + NB;
        float* out_na = out_recv + NB;
        int oj = s_ord[lane];
        int gj = s_gidx[oj];
#pragma unroll
        for (int rr = 0; rr < 4; rr++) {
            int srow = w * 4 + rr;
            int oi = s_ord[srow];
            int gi = s_gidx[oi];
            float f = smf[FLOWW + srow * 32 + lane];
            unsigned ab = s_actb[srow];
            if ((ab >> lane) & 1u) {
                out_sh[(size_t)gi * NB + gj] = f;
                out_ef[(size_t)gi * NB + gj] = smf[EFFW + oi * 32 + oj];
            }
            float v = f;
#pragma unroll
            for (int o = 16; o > 0; o >>= 1) v += __shfl_xor_sync(0xffffffffu, v, o);
            if (lane == 0) {
                out_sent[gi] = v;
                float dnl = smf[DNETW + srow];
                out_recv[gi] = dnl - smf[NSRTW + srow];
                out_na[gi] = dnl;
                smf[RSENTW + srow] = v;
            }
        }
    }
    __syncthreads();

    // ================= J. per-cluster total + last-block global sum ========
    if (t == 0) {
        float tot = 0.f;
#pragma unroll
        for (int i = 0; i < 32; i++) tot += smf[RSENTW + i];
        d_partial[c] = tot;
        __threadfence();
        unsigned old = atomicAdd(&d_ticket, 1u);
        if (old == NC - 1) {
            __threadfence();
            float s0 = 0.f, s1 = 0.f, s2 = 0.f, s3 = 0.f;
#pragma unroll 8
            for (int q = 0; q < NC; q += 4) {
                s0 += __ldcg(d_partial + q);
                s1 += __ldcg(d_partial + q + 1);
                s2 += __ldcg(d_partial + q + 2);
                s3 += __ldcg(d_partial + q + 3);
            }
            out[2 * MATSZ] = (s0 + s1) + (s2 + s3);
            d_ticket = 0;   // reset for next graph replay
        }
    }
}

// ------------------------------------------------------------------------------
extern "C" void kernel_launch(void* const* d_in, const int* in_sizes, int n_in,
                              void* d_out, int out_size) {
    const float* emb   = (const float*)d_in[0];
    const float* gen   = (const float*)d_in[1];
    const float* cons  = (const float*)d_in[2];
    const float* pos   = (const float*)d_in[3];
    const float* fpw1  = (const float*)d_in[4];
    const float* fpb1  = (const float*)d_in[5];
    const float* fpw2  = (const float*)d_in[6];
    const float* fpb2  = (const float*)d_in[7];
    const float* fpw3  = (const float*)d_in[8];
    const float* fpb3  = (const float*)d_in[9];
    const float* enw1  = (const float*)d_in[10];
    const float* enb1  = (const float*)d_in[11];
    const float* enw2  = (const float*)d_in[12];
    const float* enb2  = (const float*)d_in[13];
    const float* psw1  = (const float*)d_in[14];
    const float* psb1  = (const float*)d_in[15];
    const float* psw2  = (const float*)d_in[16];
    const float* psb2  = (const float*)d_in[17];
    const int*   assign = (const int*)d_in[18];
    const int*   hour   = (n_in >= 21) ? (const int*)d_in[20] : nullptr;
    float* out = (float*)d_out;

    cudaFuncSetAttribute(mega_kernel,
                         cudaFuncAttributeMaxDynamicSharedMemorySize, SM_BYTES);

    mega_kernel<<<NC, 256, SM_BYTES>>>(emb, gen, cons, pos,
                                       fpw1, fpb1, fpw2, fpb2, fpw3, fpb3,
                                       enw1, enb1, enw2, enb2,
                                       psw1, psb1, psw2, psb2,
                                       assign, hour, out);
}

// round 5
// speedup vs baseline: 1.0234x; 1.0234x over previous
#include <cuda_runtime.h>
#include <math.h>

#define NB 4096
#define NC 128
#define KC 32
#define ED 128
#define MATSZ 16777216ULL   // 4096*4096
#define NT 512

__device__ float d_partial[NC];
__device__ unsigned d_ticket;   // zero-init; last block resets

typedef unsigned long long u64;

__device__ __forceinline__ u64 fma2(u64 a, u64 b, u64 c) {
    u64 d;
    asm("fma.rn.f32x2 %0, %1, %2, %3;" : "=l"(d) : "l"(a), "l"(b), "l"(c));
    return d;
}
#define PK2(v, lo, hi)   asm("mov.b64 %0, {%1, %2};" : "=l"(v) : "f"(lo), "f"(hi))
#define UNPK2(lo, hi, v) asm("mov.b64 {%0, %1}, %2;" : "=f"(lo), "=f"(hi) : "l"(v))

// ---- dynamic smem word offsets -------------------------------------------
#define A_W    0        // 8448 w: emb row-stage (prologue) -> w2p u64[64*66] (main)
#define B_W    8448     // 8192 w: w1p chunks / psw1T (prologue) -> h1p u64[2048]
#define SPART  12544    // 256 w (after h1p's 4096 w inside B)
#define HIT    16640    // 4224 w  hiT[k*33 + i]
#define HJT    20864    // 4224 w  hjT[k*33 + j]
#define DISTW  25088    // 1024
#define EFFW   26112    // 1024
#define PFW    27136    // 1024
#define FLOWW  28160    // 1024
#define CVW    29184    // 128
#define W1DW   29312    // 128
#define GIDX   29440    // int[32]
#define NETW   29472
#define PRIOW  29504
#define ORDW   29536
#define ACTBW  29568
#define DNETW  29600
#define NSRTW  29632
#define RSENTW 29664
#define WCNTW  29696    // int[16]
#define POSW   29712    // float2[32] = 64 w (8B aligned)
#define EMBT   29776    // 4224 w  embT[k*33 + r]
#define SM_WORDS 34000
#define SM_BYTES (SM_WORDS * 4)

__global__ void __launch_bounds__(NT, 1) mega_kernel(
    const float* __restrict__ emb,  const float* __restrict__ gen,
    const float* __restrict__ cons, const float* __restrict__ pos,
    const float* __restrict__ fpw1, const float* __restrict__ fpb1,
    const float* __restrict__ fpw2, const float* __restrict__ fpb2,
    const float* __restrict__ fpw3, const float* __restrict__ fpb3,
    const float* __restrict__ enw1, const float* __restrict__ enb1,
    const float* __restrict__ enw2, const float* __restrict__ enb2,
    const float* __restrict__ psw1, const float* __restrict__ psb1,
    const float* __restrict__ psw2, const float* __restrict__ psb2,
    const int* __restrict__ assign, const int* __restrict__ hour_p,
    float* __restrict__ out) {
    extern __shared__ float smf[];
    int* s_gidx = (int*)(smf + GIDX);
    int* s_ord  = (int*)(smf + ORDW);
    unsigned* s_actb = (unsigned*)(smf + ACTBW);
    int* s_wcnt = (int*)(smf + WCNTW);
    float2* s_pos2 = (float2*)(smf + POSW);
    float* s_part = smf + SPART;

    const int c = blockIdx.x;
    const int t = threadIdx.x;
    const int w = t >> 5, lane = t & 31;
    const int hour = hour_p ? *hour_p : 12;

    // ================= A. stable grouping (16 warps, 2-pass ballot) ========
    {
        int a[8];
        const int* ap = assign + w * 256;
#pragma unroll
        for (int q = 0; q < 8; q++) a[q] = ap[q * 32 + lane];
        unsigned balls[8];
        int cnt = 0;
#pragma unroll
        for (int q = 0; q < 8; q++) {
            balls[q] = __ballot_sync(0xffffffffu, a[q] == c);
            cnt += __popc(balls[q]);
        }
        if (lane == 0) s_wcnt[w] = cnt;
        __syncthreads();
        int run = 0;
        for (int ww = 0; ww < 16; ww++) if (ww < w) run += s_wcnt[ww];
#pragma unroll
        for (int q = 0; q < 8; q++) {
            if (a[q] == c) {
                int p = run + __popc(balls[q] & ((1u << lane) - 1u));
                if (p < KC) s_gidx[p] = w * 256 + q * 32 + lane;
            }
            run += __popc(balls[q]);
        }
    }
    __syncthreads();

    // ================= B. net, positions, cv/w1d, emb stage ================
    if (t < KC) {
        int b = s_gidx[t];
        smf[NETW + t] = gen[b * 24 + hour] - cons[b * 24 + hour];
        s_pos2[t] = make_float2(pos[b * 2], pos[b * 2 + 1]);
    }
    {
        float hour_f = (float)hour * (1.f / 24.f);
        if (t >= 256 && t < 384) {
            int k = t - 256;
            smf[W1DW + k] = fpw1[(size_t)k * 258 + 256];
            smf[CVW + k] = fmaf(hour_f, fpw1[(size_t)k * 258 + 257], fpb1[k]);
        }
        // coalesced emb rows into A (stride 129), then transpose to embT
        for (int i = t; i < 4096; i += NT) {
            int r = i >> 7, k = i & 127;
            smf[A_W + r * 129 + k] = emb[(size_t)s_gidx[r] * ED + k];
        }
    }
    __syncthreads();
    for (int i = t; i < 4096; i += NT) {
        int k = i >> 5, r = i & 31;
        smf[EMBT + k * 33 + r] = smf[A_W + r * 129 + k];
    }

    // ================= C. hij GEMM: lane=row, warp covers 16 out-cols ======
    {
        u64 acc[8];
#pragma unroll
        for (int u = 0; u < 8; u++) acc[u] = 0ull;
        for (int kc = 0; kc < 4; kc++) {
            __syncthreads();
            // stage w1p chunk: float layout [kk][cc] (cc = packed out col)
            for (int f = t; f < 8192; f += NT) {
                int kk = f >> 8, cc = f & 255;
                float v = (cc < 128)
                    ? fpw1[(size_t)cc * 258 + kc * 32 + kk]
                    : fpw1[(size_t)(cc - 128) * 258 + 128 + kc * 32 + kk];
                smf[B_W + kk * 256 + cc] = v;
            }
            __syncthreads();
            const u64* w1u = (const u64*)(smf + B_W);
#pragma unroll 4
            for (int kk = 0; kk < 32; kk++) {
                int k = kc * 32 + kk;
                float e = smf[EMBT + k * 33 + lane];
                u64 e2; PK2(e2, e, e);
                const ulonglong2* wr = (const ulonglong2*)(w1u + kk * 128 + w * 8);
                ulonglong2 q0 = wr[0], q1 = wr[1], q2 = wr[2], q3 = wr[3];
                acc[0] = fma2(e2, q0.x, acc[0]);
                acc[1] = fma2(e2, q0.y, acc[1]);
                acc[2] = fma2(e2, q1.x, acc[2]);
                acc[3] = fma2(e2, q1.y, acc[3]);
                acc[4] = fma2(e2, q2.x, acc[4]);
                acc[5] = fma2(e2, q2.y, acc[5]);
                acc[6] = fma2(e2, q3.x, acc[6]);
                acc[7] = fma2(e2, q3.y, acc[7]);
            }
        }
        __syncthreads();
#pragma unroll
        for (int u = 0; u < 8; u++) {
            int pc = w * 8 + u;          // out-col pair (2pc, 2pc+1)
            float lo, hi;
            UNPK2(lo, hi, acc[u]);
            if (pc < 64) {
                smf[HIT + (2 * pc) * 33 + lane] = lo;
                smf[HIT + (2 * pc + 1) * 33 + lane] = hi;
            } else {
                smf[HJT + (2 * pc - 128) * 33 + lane] = lo;
                smf[HJT + (2 * pc - 127) * 33 + lane] = hi;
            }
        }
    }
    __syncthreads();

    // ================= D. priority MLP (16 warps x 2 rows) =================
    {
        float* s_pT = smf + B_W;      // psw1T [e*33+m]
        for (int i = t; i < 4096; i += NT) {
            int m = i >> 7, e = i & 127;
            s_pT[e * 33 + m] = psw1[i];
        }
        __syncthreads();
        float b1m = psb1[lane], w2m = psw2[lane], b2s = psb2[0];
#pragma unroll
        for (int rr = 0; rr < 2; rr++) {
            int r = w * 2 + rr;
            float acc = b1m;
#pragma unroll 8
            for (int e = 0; e < 128; e++)
                acc = fmaf(smf[EMBT + e * 33 + r], s_pT[e * 33 + lane], acc);
            float v = fmaxf(acc, 0.f) * w2m;
#pragma unroll
            for (int o = 16; o > 0; o >>= 1) v += __shfl_xor_sync(0xffffffffu, v, o);
            if (lane == 0) smf[PRIOW + r] = 1.f / (1.f + expf(-(v + b2s)));
        }
    }

    // ================= E. dist + efficiency ================================
    {
        float b2v = enb2[0];
        for (int pp = t; pp < 1024; pp += NT) {
            int i = pp >> 5, j = pp & 31;
            float2 pi = s_pos2[i], pj = s_pos2[j];
            float dx = pi.x - pj.x, dy = pi.y - pj.y;
            float dist = sqrtf(dx * dx + dy * dy);
            float tq = dist * (1.f / 1000.f);
            float s = 0.f;
#pragma unroll
            for (int l = 0; l < 16; l++)
                s = fmaf(fmaxf(fmaf(tq, __ldg(enw1 + l), __ldg(enb1 + l)), 0.f),
                         __ldg(enw2 + l), s);
            smf[EFFW + pp] = 0.85f + 0.13f / (1.f + expf(-(s + b2v)));
            smf[DISTW + pp] = dist;
        }
    }
    __syncthreads();

    // ================= F. stage w2p (k-pair packed, stride 66 u64) =========
    {
        float2* w2p = (float2*)(smf + A_W);
        for (int idx = t; idx < 4096; idx += NT) {
            int kp = idx & 63, n = idx >> 6;   // coalesced LDG over kp
            w2p[kp * 66 + n] = *(const float2*)(fpw2 + n * 128 + 2 * kp);
        }
    }

    // consumer constants: warp = (nslice 0..7) x (jhalf 0..1)
    const int nslice = w >> 1, jhalf = w & 1;
    const int jp = lane & 15, nh = lane >> 4;
    const int jj = jhalf * 16 + jp;            // this thread's j
    const int nb = nslice * 8 + nh * 4;        // 4 n values
    float4 w3q = *(const float4*)(fpw3 + nb);
    u64 b2p0, b2p1, b2p2, b2p3;
    {
        float4 b2q = *(const float4*)(fpb2 + nb);
        PK2(b2p0, b2q.x, 0.f); PK2(b2p1, b2q.y, 0.f);
        PK2(b2p2, b2q.z, 0.f); PK2(b2p3, b2q.w, 0.f);
    }
    float b3 = fpb3[0];
    __syncthreads();

    // ================= G. mainloop over senders i ==========================
    {
        float2* h1p2 = (float2*)(smf + B_W);      // slot kp*32 + j
        const u64* h1u = (const u64*)(smf + B_W);
        const u64* w2u = (const u64*)(smf + A_W);
        const float4 z4 = make_float4(0.f, 0.f, 0.f, 0.f);
        const float4 o4 = make_float4(1.f, 1.f, 1.f, 1.f);
        float4* outS4 = (float4*)out;
        float4* outE4 = (float4*)(out + MATSZ);

        for (int i = 0; i < 32; i++) {
            // ---- deferred pf reduce for i-1 (threads 0..255) --------------
            if (i > 0 && t < 256) {
                int jr = t >> 3, sw = t & 7;
                float v = s_part[sw * 32 + jr];
                v += __shfl_xor_sync(0xffffffffu, v, 1);
                v += __shfl_xor_sync(0xffffffffu, v, 2);
                v += __shfl_xor_sync(0xffffffffu, v, 4);
                if (sw == 0) {
                    float x = v + b3;
                    smf[PFW + (i - 1) * 32 + jr] = (x > 20.f) ? x : log1pf(expf(x));
                }
            }
            // ---- producer: warp w covers kp in [w*4, w*4+4), lane = j -----
            {
                float dd = smf[DISTW + i * 32 + lane];
#pragma unroll
                for (int s = 0; s < 4; s++) {
                    int kp = w * 4 + s, k0 = 2 * kp, k1 = k0 + 1;
                    float h0 = smf[HIT + k0 * 33 + i] + smf[HJT + k0 * 33 + lane]
                             + fmaf(dd, smf[W1DW + k0], smf[CVW + k0]);
                    float h1 = smf[HIT + k1 * 33 + i] + smf[HJT + k1 * 33 + lane]
                             + fmaf(dd, smf[W1DW + k1], smf[CVW + k1]);
                    h1p2[kp * 32 + lane] =
                        make_float2(fmaxf(h0, 0.f), fmaxf(h1, 0.f));
                }
            }
            // ---- fill this sender's output row (default values) -----------
            {
                size_t rb = (size_t)s_gidx[i] * 1024;
                outS4[rb + t] = z4;          outS4[rb + 512 + t] = z4;
                outE4[rb + t] = o4;          outE4[rb + 512 + t] = o4;
            }
            __syncthreads();

            // ---- consumer GEMM: 1 j x 4 n, k-pair packed FFMA2 ------------
            u64 a0 = b2p0, a1 = b2p1, a2 = b2p2, a3 = b2p3;
#pragma unroll 8
            for (int kp = 0; kp < 64; kp++) {
                u64 h = h1u[kp * 32 + jj];
                ulonglong2 wv = *(const ulonglong2*)(w2u + kp * 66 + nb);
                a0 = fma2(h, wv.x, a0);
                a1 = fma2(h, wv.y, a1);
                ulonglong2 wv2 = *(const ulonglong2*)(w2u + kp * 66 + nb + 2);
                a2 = fma2(h, wv2.x, a2);
                a3 = fma2(h, wv2.y, a3);
            }
            // ---- epilogue: h2 = lo+hi, relu, dot w3, fold nh halves -------
            float lo, hi, v;
            UNPK2(lo, hi, a0); v = fmaxf(lo + hi, 0.f) * w3q.x;
            UNPK2(lo, hi, a1); v = fmaf(fmaxf(lo + hi, 0.f), w3q.y, v);
            UNPK2(lo, hi, a2); v = fmaf(fmaxf(lo + hi, 0.f), w3q.z, v);
            UNPK2(lo, hi, a3); v = fmaf(fmaxf(lo + hi, 0.f), w3q.w, v);
            v += __shfl_xor_sync(0xffffffffu, v, 16);
            if (lane < 16) s_part[nslice * 32 + jj] = v;
            __syncthreads();
        }
        // final pf reduce for i = 31
        if (t < 256) {
            int jr = t >> 3, sw = t & 7;
            float v = s_part[sw * 32 + jr];
            v += __shfl_xor_sync(0xffffffffu, v, 1);
            v += __shfl_xor_sync(0xffffffffu, v, 2);
            v += __shfl_xor_sync(0xffffffffu, v, 4);
            if (sw == 0) {
                float x = v + b3;
                smf[PFW + 31 * 32 + jr] = (x > 20.f) ? x : log1pf(expf(x));
            }
        }
    }
    __syncthreads();

    // ================= H. greedy (warp 0, prefix-scan water-filling) =======
    if (w == 0) {
        float pr = smf[PRIOW + lane];
        int r = 0;
#pragma unroll
        for (int l = 0; l < KC; l++) {
            float q = smf[PRIOW + l];
            r += (q > pr) || (q == pr && l < lane);
        }
        s_ord[r] = lane;
        __syncwarp();
        int oj = s_ord[lane];
        float nets = smf[NETW + oj];
        float dn = nets;
        for (int i = 0; i < 32; i++) {
            int oi = s_ord[i];
            float A = fmaxf(__shfl_sync(0xffffffffu, nets, i), 0.f);
            float needed = -dn;
            float pf = smf[PFW + oi * 32 + oj];
            float cap = (needed > 0.f) ? fminf(needed, pf) : 0.f;
            float C = cap;
#pragma unroll
            for (int o = 1; o < 32; o <<= 1) {
                float x = __shfl_up_sync(0xffffffffu, C, o);
                if (lane >= o) C += x;
            }
            float Cprev = C - cap;
            float avail = A - Cprev;
            bool act = (avail > 0.f) && (needed > 0.f);
            float f = act ? fminf(fminf(avail, needed), pf) : 0.f;
            dn += f * smf[EFFW + oi * 32 + oj];
            smf[FLOWW + i * 32 + lane] = f;
            unsigned ab = __ballot_sync(0xffffffffu, act);
            if (lane == 0) s_actb[i] = ab;
        }
        smf[DNETW + lane] = dn;
        smf[NSRTW + lane] = nets;
    }
    __syncthreads();

    // ================= I. scatter (16 warps x 2 rows) ======================
    {
        float* out_sh = out;
        float* out_ef = out + MATSZ;
        float* out_sent = out + 2 * MATSZ + 1;
        float* out_recv = out_sent + NB;
        float* out_na = out_recv + NB;
        int oj = s_ord[lane];
        int gj = s_gidx[oj];
#pragma unroll
        for (int rr = 0; rr < 2; rr++) {
            int srow = w * 2 + rr;
            int oi = s_ord[srow];
            int gi = s_gidx[oi];
            float f = smf[FLOWW + srow * 32 + lane];
            unsigned ab = s_actb[srow];
            if ((ab >> lane) & 1u) {
                out_sh[(size_t)gi * NB + gj] = f;
                out_ef[(size_t)gi * NB + gj] = smf[EFFW + oi * 32 + oj];
            }
            float v = f;
#pragma unroll
            for (int o = 16; o > 0; o >>= 1) v += __shfl_xor_sync(0xffffffffu, v, o);
            if (lane == 0) {
                out_sent[gi] = v;
                float dnl = smf[DNETW + srow];
                out_recv[gi] = dnl - smf[NSRTW + srow];
                out_na[gi] = dnl;
                smf[RSENTW + srow] = v;
            }
        }
    }
    __syncthreads();

    // ================= J. per-cluster total + last-block global sum ========
    if (t == 0) {
        float tot = 0.f;
#pragma unroll
        for (int i = 0; i < 32; i++) tot += smf[RSENTW + i];
        d_partial[c] = tot;
        __threadfence();
        unsigned old = atomicAdd(&d_ticket, 1u);
        if (old == NC - 1) {
            __threadfence();
            float s0 = 0.f, s1 = 0.f, s2 = 0.f, s3 = 0.f;
#pragma unroll 8
            for (int q = 0; q < NC; q += 4) {
                s0 += __ldcg(d_partial + q);
                s1 += __ldcg(d_partial + q + 1);
                s2 += __ldcg(d_partial + q + 2);
                s3 += __ldcg(d_partial + q + 3);
            }
            out[2 * MATSZ] = (s0 + s1) + (s2 + s3);
            d_ticket = 0;   // reset for next graph replay
        }
    }
}

// ------------------------------------------------------------------------------
extern "C" void kernel_launch(void* const* d_in, const int* in_sizes, int n_in,
                              void* d_out, int out_size) {
    const float* emb   = (const float*)d_in[0];
    const float* gen   = (const float*)d_in[1];
    const float* cons  = (const float*)d_in[2];
    const float* pos   = (const float*)d_in[3];
    const float* fpw1  = (const float*)d_in[4];
    const float* fpb1  = (const float*)d_in[5];
    const float* fpw2  = (const float*)d_in[6];
    const float* fpb2  = (const float*)d_in[7];
    const float* fpw3  = (const float*)d_in[8];
    const float* fpb3  = (const float*)d_in[9];
    const float* enw1  = (const float*)d_in[10];
    const float* enb1  = (const float*)d_in[11];
    const float* enw2  = (const float*)d_in[12];
    const float* enb2  = (const float*)d_in[13];
    const float* psw1  = (const float*)d_in[14];
    const float* psb1  = (const float*)d_in[15];
    const float* psw2  = (const float*)d_in[16];
    const float* psb2  = (const float*)d_in[17];
    const int*   assign = (const int*)d_in[18];
    const int*   hour   = (n_in >= 21) ? (const int*)d_in[20] : nullptr;
    float* out = (float*)d_out;

    cudaFuncSetAttribute(mega_kernel,
                         cudaFuncAttributeMaxDynamicSharedMemorySize, SM_BYTES);

    mega_kernel<<<NC, NT, SM_BYTES>>>(emb, gen, cons, pos,
                                      fpw1, fpb1, fpw2, fpb2, fpw3, fpb3,
                                      enw1, enb1, enw2, enb2,
                                      psw1, psb1, psw2, psb2,
                                      assign, hour, out);
}

// round 6
// speedup vs baseline: 1.2387x; 1.2104x over previous
#include <cuda_runtime.h>
#include <math.h>

#define NB 4096
#define NC 128
#define KC 32
#define ED 128
#define MATSZ 16777216ULL   // 4096*4096
#define NT 512

__device__ float d_partial[NC];
__device__ unsigned d_ticket;   // zero-init; last block resets

typedef unsigned long long u64;

__device__ __forceinline__ u64 fma2(u64 a, u64 b, u64 c) {
    u64 d;
    asm("fma.rn.f32x2 %0, %1, %2, %3;" : "=l"(d) : "l"(a), "l"(b), "l"(c));
    return d;
}
#define PK2(v, lo, hi)   asm("mov.b64 %0, {%1, %2};" : "=l"(v) : "f"(lo), "f"(hi))
#define UNPK2(lo, hi, v) asm("mov.b64 {%0, %1}, %2;" : "=f"(lo), "=f"(hi) : "l"(v))

// ---- dynamic smem word offsets -------------------------------------------
#define A_W    0        // 8448 w: emb row-stage (prologue) -> w2p u64[64*66]
#define H1A    8448     // 4096 w: u64[2048]   (B region = w1p/psw1T staging in prologue)
#define H1B    12544    // 4096 w: u64[2048]
#define SPARTW 16640    // 520 w (stride 65 x 8)
#define HIT    17160    // 4224 w  hiT[k*33 + i]
#define HJT    21384    // 4224 w  hjT[k*33 + j]  (later merged with cv)
#define DISTW  25608    // 1024
#define EFFW   26632    // 1024
#define PFW    27656    // 1024
#define FLOWW  28680    // 1024
#define CVW    29704    // 128
#define W1DW   29832    // 128
#define GIDX   29960    // int[32]
#define NETW   29992
#define PRIOW  30024
#define ORDW   30056
#define ACTBW  30088
#define DNETW  30120
#define NSRTW  30152
#define RSENTW 30184
#define WCNTW  30216    // int[16]
#define POSW   30232    // float2[32] = 64 w (8B aligned)
#define EMBT   30296    // 4224 w  embT[k*33 + r]
#define SM_WORDS 34520
#define SM_BYTES (SM_WORDS * 4)

__global__ void __launch_bounds__(NT, 1) mega_kernel(
    const float* __restrict__ emb,  const float* __restrict__ gen,
    const float* __restrict__ cons, const float* __restrict__ pos,
    const float* __restrict__ fpw1, const float* __restrict__ fpb1,
    const float* __restrict__ fpw2, const float* __restrict__ fpb2,
    const float* __restrict__ fpw3, const float* __restrict__ fpb3,
    const float* __restrict__ enw1, const float* __restrict__ enb1,
    const float* __restrict__ enw2, const float* __restrict__ enb2,
    const float* __restrict__ psw1, const float* __restrict__ psb1,
    const float* __restrict__ psw2, const float* __restrict__ psb2,
    const int* __restrict__ assign, const int* __restrict__ hour_p,
    float* __restrict__ out) {
    extern __shared__ float smf[];
    int* s_gidx = (int*)(smf + GIDX);
    int* s_ord  = (int*)(smf + ORDW);
    unsigned* s_actb = (unsigned*)(smf + ACTBW);
    int* s_wcnt = (int*)(smf + WCNTW);
    float2* s_pos2 = (float2*)(smf + POSW);
    float* s_part = smf + SPARTW;

    const int c = blockIdx.x;
    const int t = threadIdx.x;
    const int w = t >> 5, lane = t & 31;
    const int hour = hour_p ? *hour_p : 12;

    // ================= A. stable grouping (16 warps, 2-pass ballot) ========
    {
        int a[8];
        const int* ap = assign + w * 256;
#pragma unroll
        for (int q = 0; q < 8; q++) a[q] = ap[q * 32 + lane];
        unsigned balls[8];
        int cnt = 0;
#pragma unroll
        for (int q = 0; q < 8; q++) {
            balls[q] = __ballot_sync(0xffffffffu, a[q] == c);
            cnt += __popc(balls[q]);
        }
        if (lane == 0) s_wcnt[w] = cnt;
        __syncthreads();
        int run = 0;
        for (int ww = 0; ww < 16; ww++) if (ww < w) run += s_wcnt[ww];
#pragma unroll
        for (int q = 0; q < 8; q++) {
            if (a[q] == c) {
                int p = run + __popc(balls[q] & ((1u << lane) - 1u));
                if (p < KC) s_gidx[p] = w * 256 + q * 32 + lane;
            }
            run += __popc(balls[q]);
        }
    }
    __syncthreads();

    // ================= B. net, positions, cv/w1d, emb stage ================
    if (t < KC) {
        int b = s_gidx[t];
        smf[NETW + t] = gen[b * 24 + hour] - cons[b * 24 + hour];
        s_pos2[t] = make_float2(pos[b * 2], pos[b * 2 + 1]);
    }
    {
        float hour_f = (float)hour * (1.f / 24.f);
        if (t >= 256 && t < 384) {
            int k = t - 256;
            smf[W1DW + k] = fpw1[(size_t)k * 258 + 256];
            smf[CVW + k] = fmaf(hour_f, fpw1[(size_t)k * 258 + 257], fpb1[k]);
        }
        for (int i = t; i < 4096; i += NT) {
            int r = i >> 7, k = i & 127;
            smf[A_W + r * 129 + k] = emb[(size_t)s_gidx[r] * ED + k];
        }
    }
    __syncthreads();
    for (int i = t; i < 4096; i += NT) {
        int k = i >> 5, r = i & 31;
        smf[EMBT + k * 33 + r] = smf[A_W + r * 129 + k];
    }

    // ================= C. hij GEMM: lane=row, warp covers 16 out-cols ======
    {
        u64 acc[8];
#pragma unroll
        for (int u = 0; u < 8; u++) acc[u] = 0ull;
        for (int kc = 0; kc < 4; kc++) {
            __syncthreads();
            for (int f = t; f < 8192; f += NT) {
                int kk = f >> 8, cc = f & 255;
                float v = (cc < 128)
                    ? fpw1[(size_t)cc * 258 + kc * 32 + kk]
                    : fpw1[(size_t)(cc - 128) * 258 + 128 + kc * 32 + kk];
                smf[H1A + kk * 256 + cc] = v;
            }
            __syncthreads();
            const u64* w1u = (const u64*)(smf + H1A);
#pragma unroll 4
            for (int kk = 0; kk < 32; kk++) {
                int k = kc * 32 + kk;
                float e = smf[EMBT + k * 33 + lane];
                u64 e2; PK2(e2, e, e);
                const ulonglong2* wr = (const ulonglong2*)(w1u + kk * 128 + w * 8);
                ulonglong2 q0 = wr[0], q1 = wr[1], q2 = wr[2], q3 = wr[3];
                acc[0] = fma2(e2, q0.x, acc[0]);
                acc[1] = fma2(e2, q0.y, acc[1]);
                acc[2] = fma2(e2, q1.x, acc[2]);
                acc[3] = fma2(e2, q1.y, acc[3]);
                acc[4] = fma2(e2, q2.x, acc[4]);
                acc[5] = fma2(e2, q2.y, acc[5]);
                acc[6] = fma2(e2, q3.x, acc[6]);
                acc[7] = fma2(e2, q3.y, acc[7]);
            }
        }
        __syncthreads();
#pragma unroll
        for (int u = 0; u < 8; u++) {
            int pc = w * 8 + u;          // out-col pair (2pc, 2pc+1)
            float lo, hi;
            UNPK2(lo, hi, acc[u]);
            if (pc < 64) {
                smf[HIT + (2 * pc) * 33 + lane] = lo;
                smf[HIT + (2 * pc + 1) * 33 + lane] = hi;
            } else {
                smf[HJT + (2 * pc - 128) * 33 + lane] = lo;
                smf[HJT + (2 * pc - 127) * 33 + lane] = hi;
            }
        }
    }
    __syncthreads();

    // ================= D. priority MLP (16 warps x 2 rows) =================
    {
        float* s_pT = smf + H1A;      // psw1T [e*33+m]
        for (int i = t; i < 4096; i += NT) {
            int m = i >> 7, e = i & 127;
            s_pT[e * 33 + m] = psw1[i];
        }
        __syncthreads();
        float b1m = psb1[lane], w2m = psw2[lane], b2s = psb2[0];
#pragma unroll
        for (int rr = 0; rr < 2; rr++) {
            int r = w * 2 + rr;
            float acc = b1m;
#pragma unroll 8
            for (int e = 0; e < 128; e++)
                acc = fmaf(smf[EMBT + e * 33 + r], s_pT[e * 33 + lane], acc);
            float v = fmaxf(acc, 0.f) * w2m;
#pragma unroll
            for (int o = 16; o > 0; o >>= 1) v += __shfl_xor_sync(0xffffffffu, v, o);
            if (lane == 0) smf[PRIOW + r] = 1.f / (1.f + expf(-(v + b2s)));
        }
    }

    // ================= E. dist + efficiency ================================
    {
        float b2v = enb2[0];
        for (int pp = t; pp < 1024; pp += NT) {
            int i = pp >> 5, j = pp & 31;
            float2 pi = s_pos2[i], pj = s_pos2[j];
            float dx = pi.x - pj.x, dy = pi.y - pj.y;
            float dist = sqrtf(dx * dx + dy * dy);
            float tq = dist * (1.f / 1000.f);
            float s = 0.f;
#pragma unroll
            for (int l = 0; l < 16; l++)
                s = fmaf(fmaxf(fmaf(tq, __ldg(enw1 + l), __ldg(enb1 + l)), 0.f),
                         __ldg(enw2 + l), s);
            smf[EFFW + pp] = 0.85f + 0.13f / (1.f + expf(-(s + b2v)));
            smf[DISTW + pp] = dist;
        }
    }
    __syncthreads();

    // ================= F. stage w2p; merge cv into hjT =====================
    {
        float2* w2p = (float2*)(smf + A_W);
        for (int idx = t; idx < 4096; idx += NT) {
            int kp = idx & 63, n = idx >> 6;   // coalesced LDG over kp
            w2p[kp * 66 + n] = *(const float2*)(fpw2 + n * 128 + 2 * kp);
        }
        // hjT[k][j] += cv[k]  (producer then needs only hi + fma(dd,w1d,hjcv))
        for (int idx = t; idx < 4096; idx += NT) {
            int k = idx >> 5, j = idx & 31;
            smf[HJT + k * 33 + j] += smf[CVW + k];
        }
    }
    __syncthreads();

    // producer constants: warp w owns k in [w*8, w*8+8)
    float w1dr[8], hjcvr[8];
#pragma unroll
    for (int s = 0; s < 8; s++) {
        w1dr[s] = smf[W1DW + w * 8 + s];
        hjcvr[s] = smf[HJT + (w * 8 + s) * 33 + lane];
    }
    // consumer constants: warp = (nslice 0..7) x (jhalf 0..1)
    const int nslice = w >> 1, jhalf = w & 1;
    const int jp = lane & 15, nh = lane >> 4;
    const int jj = jhalf * 16 + jp;            // this thread's j
    const int nb = nslice * 8 + nh * 4;        // 4 n values
    float4 w3q = *(const float4*)(fpw3 + nb);
    float4 b2q = *(const float4*)(fpb2 + nb);
    float b3 = fpb3[0];

    // ================= G. mainloop: 2 senders per iteration ================
    {
        float2* h1p2A = (float2*)(smf + H1A);
        float2* h1p2B = (float2*)(smf + H1B);
        const u64* h1uA = (const u64*)(smf + H1A);
        const u64* h1uB = (const u64*)(smf + H1B);
        const u64* w2u = (const u64*)(smf + A_W);
        const float4 z4 = make_float4(0.f, 0.f, 0.f, 0.f);
        const float4 o4 = make_float4(1.f, 1.f, 1.f, 1.f);
        float4* outS4 = (float4*)out;
        float4* outE4 = (float4*)(out + MATSZ);

        for (int it = 0; it < 16; it++) {
            int i0 = 2 * it, i1 = i0 + 1;
            // ---- deferred pf reduce for previous pair ---------------------
            if (it > 0) {
                int comb = t >> 3, sw = t & 7;
                float v = s_part[sw * 65 + comb];
                v += __shfl_xor_sync(0xffffffffu, v, 1);
                v += __shfl_xor_sync(0xffffffffu, v, 2);
                v += __shfl_xor_sync(0xffffffffu, v, 4);
                if (sw == 0) {
                    float x = v + b3;
                    smf[PFW + (2 * (it - 1) + (comb >> 5)) * 32 + (comb & 31)] =
                        (x > 20.f) ? x : log1pf(expf(x));
                }
            }
            // ---- producer: warp w covers kp [w*4, w*4+4), lane = j --------
            {
                float ddA = smf[DISTW + i0 * 32 + lane];
                float ddB = smf[DISTW + i1 * 32 + lane];
#pragma unroll
                for (int s = 0; s < 4; s++) {
                    int kp = w * 4 + s;
                    int l0 = 2 * s, l1 = 2 * s + 1;
                    int k0 = w * 8 + l0, k1 = k0 + 1;
                    float hiA0 = smf[HIT + k0 * 33 + i0];
                    float hiA1 = smf[HIT + k1 * 33 + i0];
                    float hiB0 = smf[HIT + k0 * 33 + i1];
                    float hiB1 = smf[HIT + k1 * 33 + i1];
                    float hA0 = fmaxf(hiA0 + fmaf(ddA, w1dr[l0], hjcvr[l0]), 0.f);
                    float hA1 = fmaxf(hiA1 + fmaf(ddA, w1dr[l1], hjcvr[l1]), 0.f);
                    float hB0 = fmaxf(hiB0 + fmaf(ddB, w1dr[l0], hjcvr[l0]), 0.f);
                    float hB1 = fmaxf(hiB1 + fmaf(ddB, w1dr[l1], hjcvr[l1]), 0.f);
                    h1p2A[kp * 32 + lane] = make_float2(hA0, hA1);
                    h1p2B[kp * 32 + lane] = make_float2(hB0, hB1);
                }
            }
            // ---- fill both senders' output rows ---------------------------
            {
                size_t rb0 = (size_t)s_gidx[i0] * 1024;
                size_t rb1 = (size_t)s_gidx[i1] * 1024;
                outS4[rb0 + t] = z4;  outS4[rb0 + 512 + t] = z4;
                outE4[rb0 + t] = o4;  outE4[rb0 + 512 + t] = o4;
                outS4[rb1 + t] = z4;  outS4[rb1 + 512 + t] = z4;
                outE4[rb1 + t] = o4;  outE4[rb1 + 512 + t] = o4;
            }
            __syncthreads();

            // ---- consumer: 2 senders x 1 j x 4 n over 64 k-pairs ----------
            u64 aA0 = 0, aA1 = 0, aA2 = 0, aA3 = 0;
            u64 aB0 = 0, aB1 = 0, aB2 = 0, aB3 = 0;
#pragma unroll 8
            for (int kp = 0; kp < 64; kp++) {
                u64 hA = h1uA[kp * 32 + jj];
                u64 hB = h1uB[kp * 32 + jj];
                ulonglong2 wv = *(const ulonglong2*)(w2u + kp * 66 + nb);
                ulonglong2 wv2 = *(const ulonglong2*)(w2u + kp * 66 + nb + 2);
                aA0 = fma2(hA, wv.x, aA0);
                aA1 = fma2(hA, wv.y, aA1);
                aA2 = fma2(hA, wv2.x, aA2);
                aA3 = fma2(hA, wv2.y, aA3);
                aB0 = fma2(hB, wv.x, aB0);
                aB1 = fma2(hB, wv.y, aB1);
                aB2 = fma2(hB, wv2.x, aB2);
                aB3 = fma2(hB, wv2.y, aB3);
            }
            // ---- epilogue: h2 = lo+hi+b2, relu, dot w3, fold nh -----------
            float lo, hi, vA, vB;
            UNPK2(lo, hi, aA0); vA = fmaxf(lo + hi + b2q.x, 0.f) * w3q.x;
            UNPK2(lo, hi, aA1); vA = fmaf(fmaxf(lo + hi + b2q.y, 0.f), w3q.y, vA);
            UNPK2(lo, hi, aA2); vA = fmaf(fmaxf(lo + hi + b2q.z, 0.f), w3q.z, vA);
            UNPK2(lo, hi, aA3); vA = fmaf(fmaxf(lo + hi + b2q.w, 0.f), w3q.w, vA);
            UNPK2(lo, hi, aB0); vB = fmaxf(lo + hi + b2q.x, 0.f) * w3q.x;
            UNPK2(lo, hi, aB1); vB = fmaf(fmaxf(lo + hi + b2q.y, 0.f), w3q.y, vB);
            UNPK2(lo, hi, aB2); vB = fmaf(fmaxf(lo + hi + b2q.z, 0.f), w3q.z, vB);
            UNPK2(lo, hi, aB3); vB = fmaf(fmaxf(lo + hi + b2q.w, 0.f), w3q.w, vB);
            vA += __shfl_xor_sync(0xffffffffu, vA, 16);
            vB += __shfl_xor_sync(0xffffffffu, vB, 16);
            if (lane < 16) {
                s_part[nslice * 65 + jj] = vA;
                s_part[nslice * 65 + 32 + jj] = vB;
            }
            __syncthreads();
        }
        // final pf reduce for senders 30, 31
        {
            int comb = t >> 3, sw = t & 7;
            float v = s_part[sw * 65 + comb];
            v += __shfl_xor_sync(0xffffffffu, v, 1);
            v += __shfl_xor_sync(0xffffffffu, v, 2);
            v += __shfl_xor_sync(0xffffffffu, v, 4);
            if (sw == 0) {
                float x = v + b3;
                smf[PFW + (30 + (comb >> 5)) * 32 + (comb & 31)] =
                    (x > 20.f) ? x : log1pf(expf(x));
            }
        }
    }
    __syncthreads();

    // ================= H. greedy (warp 0, prefix-scan water-filling) =======
    if (w == 0) {
        float pr = smf[PRIOW + lane];
        int r = 0;
#pragma unroll
        for (int l = 0; l < KC; l++) {
            float q = smf[PRIOW + l];
            r += (q > pr) || (q == pr && l < lane);
        }
        s_ord[r] = lane;
        __syncwarp();
        int oj = s_ord[lane];
        float nets = smf[NETW + oj];
        float dn = nets;
        for (int i = 0; i < 32; i++) {
            int oi = s_ord[i];
            float A = fmaxf(__shfl_sync(0xffffffffu, nets, i), 0.f);
            float needed = -dn;
            float pf = smf[PFW + oi * 32 + oj];
            float cap = (needed > 0.f) ? fminf(needed, pf) : 0.f;
            float C = cap;
#pragma unroll
            for (int o = 1; o < 32; o <<= 1) {
                float x = __shfl_up_sync(0xffffffffu, C, o);
                if (lane >= o) C += x;
            }
            float Cprev = C - cap;
            float avail = A - Cprev;
            bool act = (avail > 0.f) && (needed > 0.f);
            float f = act ? fminf(fminf(avail, needed), pf) : 0.f;
            dn += f * smf[EFFW + oi * 32 + oj];
            smf[FLOWW + i * 32 + lane] = f;
            unsigned ab = __ballot_sync(0xffffffffu, act);
            if (lane == 0) s_actb[i] = ab;
        }
        smf[DNETW + lane] = dn;
        smf[NSRTW + lane] = nets;
    }
    __syncthreads();

    // ================= I. scatter (16 warps x 2 rows) ======================
    {
        float* out_sh = out;
        float* out_ef = out + MATSZ;
        float* out_sent = out + 2 * MATSZ + 1;
        float* out_recv = out_sent + NB;
        float* out_na = out_recv + NB;
        int oj = s_ord[lane];
        int gj = s_gidx[oj];
#pragma unroll
        for (int rr = 0; rr < 2; rr++) {
            int srow = w * 2 + rr;
            int oi = s_ord[srow];
            int gi = s_gidx[oi];
            float f = smf[FLOWW + srow * 32 + lane];
            unsigned ab = s_actb[srow];
            if ((ab >> lane) & 1u) {
                out_sh[(size_t)gi * NB + gj] = f;
                out_ef[(size_t)gi * NB + gj] = smf[EFFW + oi * 32 + oj];
            }
            float v = f;
#pragma unroll
            for (int o = 16; o > 0; o >>= 1) v += __shfl_xor_sync(0xffffffffu, v, o);
            if (lane == 0) {
                out_sent[gi] = v;
                float dnl = smf[DNETW + srow];
                out_recv[gi] = dnl - smf[NSRTW + srow];
                out_na[gi] = dnl;
                smf[RSENTW + srow] = v;
            }
        }
    }
    __syncthreads();

    // ================= J. per-cluster total + last-block global sum ========
    if (t == 0) {
        float tot = 0.f;
#pragma unroll
        for (int i = 0; i < 32; i++) tot += smf[RSENTW + i];
        d_partial[c] = tot;
        __threadfence();
        unsigned old = atomicAdd(&d_ticket, 1u);
        if (old == NC - 1) {
            __threadfence();
            float s0 = 0.f, s1 = 0.f, s2 = 0.f, s3 = 0.f;
#pragma unroll 8
            for (int q = 0; q < NC; q += 4) {
                s0 += __ldcg(d_partial + q);
                s1 += __ldcg(d_partial + q + 1);
                s2 += __ldcg(d_partial + q + 2);
                s3 += __ldcg(d_partial + q + 3);
            }
            out[2 * MATSZ] = (s0 + s1) + (s2 + s3);
            d_ticket = 0;   // reset for next graph replay
        }
    }
}

// ------------------------------------------------------------------------------
extern "C" void kernel_launch(void* const* d_in, const int* in_sizes, int n_in,
                              void* d_out, int out_size) {
    const float* emb   = (const float*)d_in[0];
    const float* gen   = (const float*)d_in[1];
    const float* cons  = (const float*)d_in[2];
    const float* pos   = (const float*)d_in[3];
    const float* fpw1  = (const float*)d_in[4];
    const float* fpb1  = (const float*)d_in[5];
    const float* fpw2  = (const float*)d_in[6];
    const float* fpb2  = (const float*)d_in[7];
    const float* fpw3  = (const float*)d_in[8];
    const float* fpb3  = (const float*)d_in[9];
    const float* enw1  = (const float*)d_in[10];
    const float* enb1  = (const float*)d_in[11];
    const float* enw2  = (const float*)d_in[12];
    const float* enb2  = (const float*)d_in[13];
    const float* psw1  = (const float*)d_in[14];
    const float* psb1  = (const float*)d_in[15];
    const float* psw2  = (const float*)d_in[16];
    const float* psb2  = (const float*)d_in[17];
    const int*   assign = (const int*)d_in[18];
    const int*   hour   = (n_in >= 21) ? (const int*)d_in[20] : nullptr;
    float* out = (float*)d_out;

    cudaFuncSetAttribute(mega_kernel,
                         cudaFuncAttributeMaxDynamicSharedMemorySize, SM_BYTES);

    mega_kernel<<<NC, NT, SM_BYTES>>>(emb, gen, cons, pos,
                                      fpw1, fpb1, fpw2, fpb2, fpw3, fpb3,
                                      enw1, enb1, enw2, enb2,
                                      psw1, psb1, psw2, psb2,
                                      assign, hour, out);
}

// round 7
// speedup vs baseline: 1.3613x; 1.0990x over previous
#include <cuda_runtime.h>
#include <math.h>

#define NB 4096
#define NC 128
#define KC 32
#define ED 128
#define MATSZ 16777216ULL   // 4096*4096
#define NT 512

__device__ float d_partial[NC];
__device__ unsigned d_ticket;   // zero-init; last block resets

typedef unsigned long long u64;

__device__ __forceinline__ u64 fma2(u64 a, u64 b, u64 c) {
    u64 d;
    asm("fma.rn.f32x2 %0, %1, %2, %3;" : "=l"(d) : "l"(a), "l"(b), "l"(c));
    return d;
}
#define PK2(v, lo, hi)   asm("mov.b64 %0, {%1, %2};" : "=l"(v) : "f"(lo), "f"(hi))
#define UNPK2(lo, hi, v) asm("mov.b64 {%0, %1}, %2;" : "=f"(lo), "=f"(hi) : "l"(v))

// ---- dynamic smem word offsets -------------------------------------------
#define W2P    0        // 8448 w: emb row-stage (prologue, stride 129) -> w2p u64[64*66]
#define H1AB   8448     // 8192 w: float4[64*32] senders (0,1) k-pair interleaved
#define H1CD   16640    // 8192 w: float4[64*32] senders (2,3)
// prologue overlays: STAGE=8448 (w1p 8192 w / psw1T 4224 w), EMBT=16640 (4224 w)
#define EMBT   16640
#define HIT    24832    // 4224 w  hiT[k*33 + i]
#define HJT    29056    // 4224 w  hjT[k*33 + j] (cv merged)
#define DISTW  33280    // 1024
#define EFFW   34304    // 1024
#define PFW    35328    // 1024
#define FLOWW  36352    // 1024
#define SPARTW 37376    // 8*132 = 1056 w
#define W1DW   38432    // 128
#define CVW    38560    // 128
#define GIDX   38688    // int[32]
#define NETW   38720
#define PRIOW  38752
#define ORDW   38784
#define ACTBW  38816
#define DNETW  38848
#define NSRTW  38880
#define RSENTW 38912
#define WCNTW  38944    // int[16]
#define POSW   38960    // float2[32] = 64 w
#define SM_WORDS 39040
#define SM_BYTES (SM_WORDS * 4)

__global__ void __launch_bounds__(NT, 1) mega_kernel(
    const float* __restrict__ emb,  const float* __restrict__ gen,
    const float* __restrict__ cons, const float* __restrict__ pos,
    const float* __restrict__ fpw1, const float* __restrict__ fpb1,
    const float* __restrict__ fpw2, const float* __restrict__ fpb2,
    const float* __restrict__ fpw3, const float* __restrict__ fpb3,
    const float* __restrict__ enw1, const float* __restrict__ enb1,
    const float* __restrict__ enw2, const float* __restrict__ enb2,
    const float* __restrict__ psw1, const float* __restrict__ psb1,
    const float* __restrict__ psw2, const float* __restrict__ psb2,
    const int* __restrict__ assign, const int* __restrict__ hour_p,
    float* __restrict__ out) {
    extern __shared__ float smf[];
    int* s_gidx = (int*)(smf + GIDX);
    int* s_ord  = (int*)(smf + ORDW);
    unsigned* s_actb = (unsigned*)(smf + ACTBW);
    int* s_wcnt = (int*)(smf + WCNTW);
    float2* s_pos2 = (float2*)(smf + POSW);
    float* s_part = smf + SPARTW;

    const int c = blockIdx.x;
    const int t = threadIdx.x;
    const int w = t >> 5, lane = t & 31;
    const int hour = hour_p ? *hour_p : 12;

    // ================= A. stable grouping (16 warps, 2-pass ballot) ========
    {
        int a[8];
        const int* ap = assign + w * 256;
#pragma unroll
        for (int q = 0; q < 8; q++) a[q] = ap[q * 32 + lane];
        unsigned balls[8];
        int cnt = 0;
#pragma unroll
        for (int q = 0; q < 8; q++) {
            balls[q] = __ballot_sync(0xffffffffu, a[q] == c);
            cnt += __popc(balls[q]);
        }
        if (lane == 0) s_wcnt[w] = cnt;
        __syncthreads();
        int run = 0;
        for (int ww = 0; ww < 16; ww++) if (ww < w) run += s_wcnt[ww];
#pragma unroll
        for (int q = 0; q < 8; q++) {
            if (a[q] == c) {
                int p = run + __popc(balls[q] & ((1u << lane) - 1u));
                if (p < KC) s_gidx[p] = w * 256 + q * 32 + lane;
            }
            run += __popc(balls[q]);
        }
    }
    __syncthreads();

    // ================= B. net, positions, cv/w1d, emb stage ================
    if (t < KC) {
        int b = s_gidx[t];
        smf[NETW + t] = gen[b * 24 + hour] - cons[b * 24 + hour];
        s_pos2[t] = make_float2(pos[b * 2], pos[b * 2 + 1]);
    }
    {
        float hour_f = (float)hour * (1.f / 24.f);
        if (t >= 256 && t < 384) {
            int k = t - 256;
            smf[W1DW + k] = fpw1[(size_t)k * 258 + 256];
            smf[CVW + k] = fmaf(hour_f, fpw1[(size_t)k * 258 + 257], fpb1[k]);
        }
        for (int i = t; i < 4096; i += NT) {
            int r = i >> 7, k = i & 127;
            smf[W2P + r * 129 + k] = emb[(size_t)s_gidx[r] * ED + k];
        }
    }
    __syncthreads();
    for (int i = t; i < 4096; i += NT) {
        int k = i >> 5, r = i & 31;
        smf[EMBT + k * 33 + r] = smf[W2P + r * 129 + k];
    }

    // ================= C. hij GEMM: lane=row, warp covers 16 out-cols ======
    {
        u64 acc[8];
#pragma unroll
        for (int u = 0; u < 8; u++) acc[u] = 0ull;
        for (int kc = 0; kc < 4; kc++) {
            __syncthreads();
            for (int f = t; f < 8192; f += NT) {
                int kk = f >> 8, cc = f & 255;
                float v = (cc < 128)
                    ? fpw1[(size_t)cc * 258 + kc * 32 + kk]
                    : fpw1[(size_t)(cc - 128) * 258 + 128 + kc * 32 + kk];
                smf[H1AB + kk * 256 + cc] = v;
            }
            __syncthreads();
            const u64* w1u = (const u64*)(smf + H1AB);
#pragma unroll 4
            for (int kk = 0; kk < 32; kk++) {
                int k = kc * 32 + kk;
                float e = smf[EMBT + k * 33 + lane];
                u64 e2; PK2(e2, e, e);
                const ulonglong2* wr = (const ulonglong2*)(w1u + kk * 128 + w * 8);
                ulonglong2 q0 = wr[0], q1 = wr[1], q2 = wr[2], q3 = wr[3];
                acc[0] = fma2(e2, q0.x, acc[0]);
                acc[1] = fma2(e2, q0.y, acc[1]);
                acc[2] = fma2(e2, q1.x, acc[2]);
                acc[3] = fma2(e2, q1.y, acc[3]);
                acc[4] = fma2(e2, q2.x, acc[4]);
                acc[5] = fma2(e2, q2.y, acc[5]);
                acc[6] = fma2(e2, q3.x, acc[6]);
                acc[7] = fma2(e2, q3.y, acc[7]);
            }
        }
        __syncthreads();
#pragma unroll
        for (int u = 0; u < 8; u++) {
            int pc = w * 8 + u;          // out-col pair (2pc, 2pc+1)
            float lo, hi;
            UNPK2(lo, hi, acc[u]);
            if (pc < 64) {
                smf[HIT + (2 * pc) * 33 + lane] = lo;
                smf[HIT + (2 * pc + 1) * 33 + lane] = hi;
            } else {
                smf[HJT + (2 * pc - 128) * 33 + lane] = lo;
                smf[HJT + (2 * pc - 127) * 33 + lane] = hi;
            }
        }
    }
    __syncthreads();

    // ================= D. priority MLP (16 warps x 2 rows) =================
    {
        float* s_pT = smf + H1AB;      // psw1T [e*33+m]
        for (int i = t; i < 4096; i += NT) {
            int m = i >> 7, e = i & 127;
            s_pT[e * 33 + m] = psw1[i];
        }
        __syncthreads();
        float b1m = psb1[lane], w2m = psw2[lane], b2s = psb2[0];
#pragma unroll
        for (int rr = 0; rr < 2; rr++) {
            int r = w * 2 + rr;
            float acc = b1m;
#pragma unroll 8
            for (int e = 0; e < 128; e++)
                acc = fmaf(smf[EMBT + e * 33 + r], s_pT[e * 33 + lane], acc);
            float v = fmaxf(acc, 0.f) * w2m;
#pragma unroll
            for (int o = 16; o > 0; o >>= 1) v += __shfl_xor_sync(0xffffffffu, v, o);
            if (lane == 0) smf[PRIOW + r] = 1.f / (1.f + expf(-(v + b2s)));
        }
    }

    // ================= E. dist + efficiency ================================
    {
        float b2v = enb2[0];
        for (int pp = t; pp < 1024; pp += NT) {
            int i = pp >> 5, j = pp & 31;
            float2 pi = s_pos2[i], pj = s_pos2[j];
            float dx = pi.x - pj.x, dy = pi.y - pj.y;
            float dist = sqrtf(dx * dx + dy * dy);
            float tq = dist * (1.f / 1000.f);
            float s = 0.f;
#pragma unroll
            for (int l = 0; l < 16; l++)
                s = fmaf(fmaxf(fmaf(tq, __ldg(enw1 + l), __ldg(enb1 + l)), 0.f),
                         __ldg(enw2 + l), s);
            smf[EFFW + pp] = 0.85f + 0.13f / (1.f + expf(-(s + b2v)));
            smf[DISTW + pp] = dist;
        }
    }
    __syncthreads();

    // ================= F. stage w2p; merge cv into hjT =====================
    {
        float2* w2p = (float2*)(smf + W2P);
        for (int idx = t; idx < 4096; idx += NT) {
            int kp = idx & 63, n = idx >> 6;   // coalesced LDG over kp
            w2p[kp * 66 + n] = *(const float2*)(fpw2 + n * 128 + 2 * kp);
        }
        for (int idx = t; idx < 4096; idx += NT) {
            int k = idx >> 5, j = idx & 31;
            smf[HJT + k * 33 + j] += smf[CVW + k];
        }
    }
    __syncthreads();

    // producer constants: warp w owns k in [w*8, w*8+8) (kp in [w*4, w*4+4))
    float w1dr[8], hjcvr[8];
#pragma unroll
    for (int s = 0; s < 8; s++) {
        w1dr[s] = smf[W1DW + w * 8 + s];
        hjcvr[s] = smf[HJT + (w * 8 + s) * 33 + lane];
    }
    // consumer constants: warp = (nq8 0..7) x (jh 0..1); lane = (jp, nh)
    const int nq8 = w >> 1, jh = w & 1;
    const int jp = lane & 15, nh = lane >> 4;
    const int jj = jh * 16 + jp;              // this thread's j
    const int n0 = nq8 * 8 + nh * 4;          // 4 n values
    float4 w3q = *(const float4*)(fpw3 + n0);
    float4 b2q = *(const float4*)(fpb2 + n0);
    float b3 = fpb3[0];

    // ================= G. mainloop: 4 senders per iteration ================
    {
        float4* bufAB = (float4*)(smf + H1AB);
        float4* bufCD = (float4*)(smf + H1CD);
        const ulonglong2* h1ab = (const ulonglong2*)(smf + H1AB);
        const ulonglong2* h1cd = (const ulonglong2*)(smf + H1CD);
        const ulonglong2* w2u2 = (const ulonglong2*)(smf + W2P);
        const float4 z4 = make_float4(0.f, 0.f, 0.f, 0.f);
        const float4 o4 = make_float4(1.f, 1.f, 1.f, 1.f);
        float4* outS4 = (float4*)out;
        float4* outE4 = (float4*)(out + MATSZ);

        for (int it = 0; it < 8; it++) {
            int i0 = 4 * it;
            // ---- deferred pf reduce for previous 4 senders (t < 128) ------
            if (it > 0 && t < 128) {
                int s = t >> 5, j = t & 31;
                float v = 0.f;
#pragma unroll
                for (int q = 0; q < 8; q++)
                    v += s_part[q * 132 + s * 33 + j];
                float x = v + b3;
                smf[PFW + (4 * (it - 1) + s) * 32 + j] =
                    (x > 20.f) ? x : log1pf(expf(x));
            }
            // ---- producer: warp w covers kp [w*4,w*4+4), lane = j ---------
            {
                float dd0 = smf[DISTW + (i0 + 0) * 32 + lane];
                float dd1 = smf[DISTW + (i0 + 1) * 32 + lane];
                float dd2 = smf[DISTW + (i0 + 2) * 32 + lane];
                float dd3 = smf[DISTW + (i0 + 3) * 32 + lane];
#pragma unroll
                for (int s = 0; s < 4; s++) {
                    int kp = w * 4 + s;
                    int l0 = 2 * s, l1 = 2 * s + 1;
                    int k0 = 2 * kp, k1 = k0 + 1;
                    float p0 = fmaf(dd0, w1dr[l0], hjcvr[l0]);
                    float p1 = fmaf(dd0, w1dr[l1], hjcvr[l1]);
                    float q0 = fmaf(dd1, w1dr[l0], hjcvr[l0]);
                    float q1 = fmaf(dd1, w1dr[l1], hjcvr[l1]);
                    float r0 = fmaf(dd2, w1dr[l0], hjcvr[l0]);
                    float r1 = fmaf(dd2, w1dr[l1], hjcvr[l1]);
                    float u0 = fmaf(dd3, w1dr[l0], hjcvr[l0]);
                    float u1 = fmaf(dd3, w1dr[l1], hjcvr[l1]);
                    float4 hab, hcd;
                    hab.x = fmaxf(smf[HIT + k0 * 33 + i0 + 0] + p0, 0.f);
                    hab.y = fmaxf(smf[HIT + k1 * 33 + i0 + 0] + p1, 0.f);
                    hab.z = fmaxf(smf[HIT + k0 * 33 + i0 + 1] + q0, 0.f);
                    hab.w = fmaxf(smf[HIT + k1 * 33 + i0 + 1] + q1, 0.f);
                    hcd.x = fmaxf(smf[HIT + k0 * 33 + i0 + 2] + r0, 0.f);
                    hcd.y = fmaxf(smf[HIT + k1 * 33 + i0 + 2] + r1, 0.f);
                    hcd.z = fmaxf(smf[HIT + k0 * 33 + i0 + 3] + u0, 0.f);
                    hcd.w = fmaxf(smf[HIT + k1 * 33 + i0 + 3] + u1, 0.f);
                    bufAB[kp * 32 + lane] = hab;
                    bufCD[kp * 32 + lane] = hcd;
                }
            }
            // ---- fill the 4 senders' output rows --------------------------
            {
#pragma unroll
                for (int s = 0; s < 4; s++) {
                    size_t rb = (size_t)s_gidx[i0 + s] * 1024;
                    outS4[rb + t] = z4;  outS4[rb + 512 + t] = z4;
                    outE4[rb + t] = o4;  outE4[rb + 512 + t] = o4;
                }
            }
            __syncthreads();

            // ---- consumer: 4 senders x 1 j x 4 n over 64 k-pairs ----------
            u64 aA0 = 0, aA1 = 0, aA2 = 0, aA3 = 0;
            u64 aB0 = 0, aB1 = 0, aB2 = 0, aB3 = 0;
            u64 aC0 = 0, aC1 = 0, aC2 = 0, aC3 = 0;
            u64 aD0 = 0, aD1 = 0, aD2 = 0, aD3 = 0;
            const int wbase = nq8 * 4 + nh * 2;
#pragma unroll 4
            for (int kp = 0; kp < 64; kp++) {
                ulonglong2 hab = h1ab[kp * 32 + jj];
                ulonglong2 hcd = h1cd[kp * 32 + jj];
                ulonglong2 w01 = w2u2[kp * 33 + wbase];
                ulonglong2 w23 = w2u2[kp * 33 + wbase + 1];
                aA0 = fma2(hab.x, w01.x, aA0);
                aA1 = fma2(hab.x, w01.y, aA1);
                aA2 = fma2(hab.x, w23.x, aA2);
                aA3 = fma2(hab.x, w23.y, aA3);
                aB0 = fma2(hab.y, w01.x, aB0);
                aB1 = fma2(hab.y, w01.y, aB1);
                aB2 = fma2(hab.y, w23.x, aB2);
                aB3 = fma2(hab.y, w23.y, aB3);
                aC0 = fma2(hcd.x, w01.x, aC0);
                aC1 = fma2(hcd.x, w01.y, aC1);
                aC2 = fma2(hcd.x, w23.x, aC2);
                aC3 = fma2(hcd.x, w23.y, aC3);
                aD0 = fma2(hcd.y, w01.x, aD0);
                aD1 = fma2(hcd.y, w01.y, aD1);
                aD2 = fma2(hcd.y, w23.x, aD2);
                aD3 = fma2(hcd.y, w23.y, aD3);
            }
            // ---- epilogue: h2 = lo+hi+b2, relu, dot w3 --------------------
            float lo, hi, vA, vB, vC, vD;
            UNPK2(lo, hi, aA0); vA = fmaxf(lo + hi + b2q.x, 0.f) * w3q.x;
            UNPK2(lo, hi, aA1); vA = fmaf(fmaxf(lo + hi + b2q.y, 0.f), w3q.y, vA);
            UNPK2(lo, hi, aA2); vA = fmaf(fmaxf(lo + hi + b2q.z, 0.f), w3q.z, vA);
            UNPK2(lo, hi, aA3); vA = fmaf(fmaxf(lo + hi + b2q.w, 0.f), w3q.w, vA);
            UNPK2(lo, hi, aB0); vB = fmaxf(lo + hi + b2q.x, 0.f) * w3q.x;
            UNPK2(lo, hi, aB1); vB = fmaf(fmaxf(lo + hi + b2q.y, 0.f), w3q.y, vB);
            UNPK2(lo, hi, aB2); vB = fmaf(fmaxf(lo + hi + b2q.z, 0.f), w3q.z, vB);
            UNPK2(lo, hi, aB3); vB = fmaf(fmaxf(lo + hi + b2q.w, 0.f), w3q.w, vB);
            UNPK2(lo, hi, aC0); vC = fmaxf(lo + hi + b2q.x, 0.f) * w3q.x;
            UNPK2(lo, hi, aC1); vC = fmaf(fmaxf(lo + hi + b2q.y, 0.f), w3q.y, vC);
            UNPK2(lo, hi, aC2); vC = fmaf(fmaxf(lo + hi + b2q.z, 0.f), w3q.z, vC);
            UNPK2(lo, hi, aC3); vC = fmaf(fmaxf(lo + hi + b2q.w, 0.f), w3q.w, vC);
            UNPK2(lo, hi, aD0); vD = fmaxf(lo + hi + b2q.x, 0.f) * w3q.x;
            UNPK2(lo, hi, aD1); vD = fmaf(fmaxf(lo + hi + b2q.y, 0.f), w3q.y, vD);
            UNPK2(lo, hi, aD2); vD = fmaf(fmaxf(lo + hi + b2q.z, 0.f), w3q.z, vD);
            UNPK2(lo, hi, aD3); vD = fmaf(fmaxf(lo + hi + b2q.w, 0.f), w3q.w, vD);
            // fold the nh halves (lane ^ 16 has same j, other 4n)
            vA += __shfl_xor_sync(0xffffffffu, vA, 16);
            vB += __shfl_xor_sync(0xffffffffu, vB, 16);
            vC += __shfl_xor_sync(0xffffffffu, vC, 16);
            vD += __shfl_xor_sync(0xffffffffu, vD, 16);
            if (nh == 0) {
                s_part[nq8 * 132 + 0 * 33 + jj] = vA;
                s_part[nq8 * 132 + 1 * 33 + jj] = vB;
                s_part[nq8 * 132 + 2 * 33 + jj] = vC;
                s_part[nq8 * 132 + 3 * 33 + jj] = vD;
            }
            __syncthreads();
        }
        // final pf reduce for senders 28..31
        if (t < 128) {
            int s = t >> 5, j = t & 31;
            float v = 0.f;
#pragma unroll
            for (int q = 0; q < 8; q++)
                v += s_part[q * 132 + s * 33 + j];
            float x = v + b3;
            smf[PFW + (28 + s) * 32 + j] = (x > 20.f) ? x : log1pf(expf(x));
        }
    }
    __syncthreads();

    // ================= H. greedy (warp 0, prefix-scan water-filling) =======
    if (w == 0) {
        float pr = smf[PRIOW + lane];
        int r = 0;
#pragma unroll
        for (int l = 0; l < KC; l++) {
            float q = smf[PRIOW + l];
            r += (q > pr) || (q == pr && l < lane);
        }
        s_ord[r] = lane;
        __syncwarp();
        int oj = s_ord[lane];
        float nets = smf[NETW + oj];
        float dn = nets;
        for (int i = 0; i < 32; i++) {
            int oi = s_ord[i];
            float A = fmaxf(__shfl_sync(0xffffffffu, nets, i), 0.f);
            float needed = -dn;
            float pf = smf[PFW + oi * 32 + oj];
            float cap = (needed > 0.f) ? fminf(needed, pf) : 0.f;
            float C = cap;
#pragma unroll
            for (int o = 1; o < 32; o <<= 1) {
                float x = __shfl_up_sync(0xffffffffu, C, o);
                if (lane >= o) C += x;
            }
            float Cprev = C - cap;
            float avail = A - Cprev;
            bool act = (avail > 0.f) && (needed > 0.f);
            float f = act ? fminf(fminf(avail, needed), pf) : 0.f;
            dn += f * smf[EFFW + oi * 32 + oj];
            smf[FLOWW + i * 32 + lane] = f;
            unsigned ab = __ballot_sync(0xffffffffu, act);
            if (lane == 0) s_actb[i] = ab;
        }
        smf[DNETW + lane] = dn;
        smf[NSRTW + lane] = nets;
    }
    __syncthreads();

    // ================= I. scatter (16 warps x 2 rows) ======================
    {
        float* out_sh = out;
        float* out_ef = out + MATSZ;
        float* out_sent = out + 2 * MATSZ + 1;
        float* out_recv = out_sent + NB;
        float* out_na = out_recv + NB;
        int oj = s_ord[lane];
        int gj = s_gidx[oj];
#pragma unroll
        for (int rr = 0; rr < 2; rr++) {
            int srow = w * 2 + rr;
            int oi = s_ord[srow];
            int gi = s_gidx[oi];
            float f = smf[FLOWW + srow * 32 + lane];
            unsigned ab = s_actb[srow];
            if ((ab >> lane) & 1u) {
                out_sh[(size_t)gi * NB + gj] = f;
                out_ef[(size_t)gi * NB + gj] = smf[EFFW + oi * 32 + oj];
            }
            float v = f;
#pragma unroll
            for (int o = 16; o > 0; o >>= 1) v += __shfl_xor_sync(0xffffffffu, v, o);
            if (lane == 0) {
                out_sent[gi] = v;
                float dnl = smf[DNETW + srow];
                out_recv[gi] = dnl - smf[NSRTW + srow];
                out_na[gi] = dnl;
                smf[RSENTW + srow] = v;
            }
        }
    }
    __syncthreads();

    // ================= J. per-cluster total + last-block global sum ========
    if (t == 0) {
        float tot = 0.f;
#pragma unroll
        for (int i = 0; i < 32; i++) tot += smf[RSENTW + i];
        d_partial[c] = tot;
        __threadfence();
        unsigned old = atomicAdd(&d_ticket, 1u);
        if (old == NC - 1) {
            __threadfence();
            float s0 = 0.f, s1 = 0.f, s2 = 0.f, s3 = 0.f;
#pragma unroll 8
            for (int q = 0; q < NC; q += 4) {
                s0 += __ldcg(d_partial + q);
                s1 += __ldcg(d_partial + q + 1);
                s2 += __ldcg(d_partial + q + 2);
                s3 += __ldcg(d_partial + q + 3);
            }
            out[2 * MATSZ] = (s0 + s1) + (s2 + s3);
            d_ticket = 0;   // reset for next graph replay
        }
    }
}

// ------------------------------------------------------------------------------
extern "C" void kernel_launch(void* const* d_in, const int* in_sizes, int n_in,
                              void* d_out, int out_size) {
    const float* emb   = (const float*)d_in[0];
    const float* gen   = (const float*)d_in[1];
    const float* cons  = (const float*)d_in[2];
    const float* pos   = (const float*)d_in[3];
    const float* fpw1  = (const float*)d_in[4];
    const float* fpb1  = (const float*)d_in[5];
    const float* fpw2  = (const float*)d_in[6];
    const float* fpb2  = (const float*)d_in[7];
    const float* fpw3  = (const float*)d_in[8];
    const float* fpb3  = (const float*)d_in[9];
    const float* enw1  = (const float*)d_in[10];
    const float* enb1  = (const float*)d_in[11];
    const float* enw2  = (const float*)d_in[12];
    const float* enb2  = (const float*)d_in[13];
    const float* psw1  = (const float*)d_in[14];
    const float* psb1  = (const float*)d_in[15];
    const float* psw2  = (const float*)d_in[16];
    const float* psb2  = (const float*)d_in[17];
    const int*   assign = (const int*)d_in[18];
    const int*   hour   = (n_in >= 21) ? (const int*)d_in[20] : nullptr;
    float* out = (float*)d_out;

    cudaFuncSetAttribute(mega_kernel,
                         cudaFuncAttributeMaxDynamicSharedMemorySize, SM_BYTES);

    mega_kernel<<<NC, NT, SM_BYTES>>>(emb, gen, cons, pos,
                                      fpw1, fpb1, fpw2, fpb2, fpw3, fpb3,
                                      enw1, enb1, enw2, enb2,
                                      psw1, psb1, psw2, psb2,
                                      assign, hour, out);
}

// round 8
// speedup vs baseline: 1.4971x; 1.0998x over previous
#include <cuda_runtime.h>
#include <math.h>

#define NB 4096
#define NC 128
#define KC 32
#define MATSZ 16777216ULL   // 4096*4096
#define NT 512

__device__ float d_partial[NC];
__device__ unsigned d_ticket;   // zero-init; last block resets

typedef unsigned long long u64;

__device__ __forceinline__ u64 fma2(u64 a, u64 b, u64 c) {
    u64 d;
    asm("fma.rn.f32x2 %0, %1, %2, %3;" : "=l"(d) : "l"(a), "l"(b), "l"(c));
    return d;
}
#define PK2(v, lo, hi)   asm("mov.b64 %0, {%1, %2};" : "=l"(v) : "f"(lo), "f"(hi))
#define UNPK2(lo, hi, v) asm("mov.b64 {%0, %1}, %2;" : "=f"(lo), "=f"(hi) : "l"(v))

#define BSYNC(id)   asm volatile("bar.sync %0, %1;"   :: "n"(id), "n"(NT) : "memory")
#define BARRIVE(id) asm volatile("bar.arrive %0, %1;" :: "n"(id), "n"(NT) : "memory")

// ---- dynamic smem word offsets -------------------------------------------
#define BUF0AB 0
#define BUF0CD 8192
#define BUF1AB 16384
#define BUF1CD 24576
#define W2P    32768
#define HIT    41216
#define HJT    45440
#define DISTW  49664
#define EFFW   50688
#define PFW    51712
#define FLOWW  52736
#define SPARTW 53760
#define W1DW   55872
#define CVW    56000
#define B2FW   56128
#define W3FW   56192
#define GIDX   56256
#define NETW   56288
#define PRIOW  56320
#define ORDW   56352
#define ACTBW  56384
#define DNETW  56416
#define NSRTW  56448
#define RSENTW 56480
#define WCNTW  56512
#define POSW   56528
#define SM_WORDS 56592
#define SM_BYTES (SM_WORDS * 4)
#define EMBT   BUF1AB

__global__ void __launch_bounds__(NT, 1) mega_kernel(
    const float* __restrict__ emb,  const float* __restrict__ gen,
    const float* __restrict__ cons, const float* __restrict__ pos,
    const float* __restrict__ fpw1, const float* __restrict__ fpb1,
    const float* __restrict__ fpw2, const float* __restrict__ fpb2,
    const float* __restrict__ fpw3, const float* __restrict__ fpb3,
    const float* __restrict__ enw1, const float* __restrict__ enb1,
    const float* __restrict__ enw2, const float* __restrict__ enb2,
    const float* __restrict__ psw1, const float* __restrict__ psb1,
    const float* __restrict__ psw2, const float* __restrict__ psb2,
    const int* __restrict__ assign, const int* __restrict__ hour_p,
    float* __restrict__ out) {
    extern __shared__ float smf[];
    int* s_gidx = (int*)(smf + GIDX);
    int* s_ord  = (int*)(smf + ORDW);
    unsigned* s_actb = (unsigned*)(smf + ACTBW);
    int* s_wcnt = (int*)(smf + WCNTW);
    float2* s_pos2 = (float2*)(smf + POSW);

    const int c = blockIdx.x;
    const int t = threadIdx.x;
    const int w = t >> 5, lane = t & 31;
    const int hour = hour_p ? *hour_p : 12;

    // ================= A. stable grouping (16 warps, 2-pass ballot) ========
    {
        int a[8];
        const int* ap = assign + w * 256;
#pragma unroll
        for (int q = 0; q < 8; q++) a[q] = ap[q * 32 + lane];
        unsigned balls[8];
        int cnt = 0;
#pragma unroll
        for (int q = 0; q < 8; q++) {
            balls[q] = __ballot_sync(0xffffffffu, a[q] == c);
            cnt += __popc(balls[q]);
        }
        if (lane == 0) s_wcnt[w] = cnt;
        __syncthreads();
        int run = 0;
        for (int ww = 0; ww < 16; ww++) if (ww < w) run += s_wcnt[ww];
#pragma unroll
        for (int q = 0; q < 8; q++) {
            if (a[q] == c) {
                int p = run + __popc(balls[q] & ((1u << lane) - 1u));
                if (p < KC) s_gidx[p] = w * 256 + q * 32 + lane;
            }
            run += __popc(balls[q]);
        }
    }
    __syncthreads();

    // ================= B. net, positions, cv/w1d/b2/w3, emb stage ==========
    if (t < KC) {
        int b = s_gidx[t];
        smf[NETW + t] = gen[b * 24 + hour] - cons[b * 24 + hour];
        s_pos2[t] = make_float2(pos[b * 2], pos[b * 2 + 1]);
    }
    {
        float hour_f = (float)hour * (1.f / 24.f);
        if (t >= 256 && t < 384) {
            int k = t - 256;
            smf[W1DW + k] = fpw1[(size_t)k * 258 + 256];
            smf[CVW + k] = fmaf(hour_f, fpw1[(size_t)k * 258 + 257], fpb1[k]);
        }
        if (t >= 384 && t < 448) {
            int n = t - 384;
            smf[B2FW + n] = fpb2[n];
            smf[W3FW + n] = fpw3[n];
        }
        for (int i = t; i < 4096; i += NT) {
            int r = i >> 7, k = i & 127;
            smf[BUF0AB + r * 129 + k] = emb[(size_t)s_gidx[r] * 128 + k];
        }
    }
    __syncthreads();
    for (int i = t; i < 4096; i += NT) {
        int k = i >> 5, r = i & 31;
        smf[EMBT + k * 33 + r] = smf[BUF0AB + r * 129 + k];
    }

    // ================= C. hij GEMM: lane=row, warp covers 16 out-cols ======
    {
        u64 acc[8];
#pragma unroll
        for (int u = 0; u < 8; u++) acc[u] = 0ull;
        for (int kc = 0; kc < 4; kc++) {
            __syncthreads();
            for (int f = t; f < 8192; f += NT) {
                int kk = f >> 8, cc = f & 255;
                float v = (cc < 128)
                    ? fpw1[(size_t)cc * 258 + kc * 32 + kk]
                    : fpw1[(size_t)(cc - 128) * 258 + 128 + kc * 32 + kk];
                smf[BUF0AB + kk * 256 + cc] = v;
            }
            __syncthreads();
            const u64* w1u = (const u64*)(smf + BUF0AB);
#pragma unroll 4
            for (int kk = 0; kk < 32; kk++) {
                int k = kc * 32 + kk;
                float e = smf[EMBT + k * 33 + lane];
                u64 e2; PK2(e2, e, e);
                const ulonglong2* wr = (const ulonglong2*)(w1u + kk * 128 + w * 8);
                ulonglong2 q0 = wr[0], q1 = wr[1], q2 = wr[2], q3 = wr[3];
                acc[0] = fma2(e2, q0.x, acc[0]);
                acc[1] = fma2(e2, q0.y, acc[1]);
                acc[2] = fma2(e2, q1.x, acc[2]);
                acc[3] = fma2(e2, q1.y, acc[3]);
                acc[4] = fma2(e2, q2.x, acc[4]);
                acc[5] = fma2(e2, q2.y, acc[5]);
                acc[6] = fma2(e2, q3.x, acc[6]);
                acc[7] = fma2(e2, q3.y, acc[7]);
            }
        }
        __syncthreads();
#pragma unroll
        for (int u = 0; u < 8; u++) {
            int pc = w * 8 + u;
            float lo, hi;
            UNPK2(lo, hi, acc[u]);
            if (pc < 64) {
                smf[HIT + (2 * pc) * 33 + lane] = lo;
                smf[HIT + (2 * pc + 1) * 33 + lane] = hi;
            } else {
                smf[HJT + (2 * pc - 128) * 33 + lane] = lo;
                smf[HJT + (2 * pc - 127) * 33 + lane] = hi;
            }
        }
    }
    __syncthreads();

    // ================= D. priority MLP (16 warps x 2 rows) =================
    {
        float* s_pT = smf + BUF0AB;
        for (int i = t; i < 4096; i += NT) {
            int m = i >> 7, e = i & 127;
            s_pT[e * 33 + m] = psw1[i];
        }
        __syncthreads();
        float b1m = psb1[lane], w2m = psw2[lane], b2s = psb2[0];
#pragma unroll
        for (int rr = 0; rr < 2; rr++) {
            int r = w * 2 + rr;
            float acc = b1m;
#pragma unroll 8
            for (int e = 0; e < 128; e++)
                acc = fmaf(smf[EMBT + e * 33 + r], s_pT[e * 33 + lane], acc);
            float v = fmaxf(acc, 0.f) * w2m;
#pragma unroll
            for (int o = 16; o > 0; o >>= 1) v += __shfl_xor_sync(0xffffffffu, v, o);
            if (lane == 0) smf[PRIOW + r] = 1.f / (1.f + expf(-(v + b2s)));
        }
    }

    // ================= E. dist + efficiency ================================
    {
        float b2v = enb2[0];
        for (int pp = t; pp < 1024; pp += NT) {
            int i = pp >> 5, j = pp & 31;
            float2 pi = s_pos2[i], pj = s_pos2[j];
            float dx = pi.x - pj.x, dy = pi.y - pj.y;
            float dist = sqrtf(dx * dx + dy * dy);
            float tq = dist * (1.f / 1000.f);
            float s = 0.f;
#pragma unroll
            for (int l = 0; l < 16; l++)
                s = fmaf(fmaxf(fmaf(tq, __ldg(enw1 + l), __ldg(enb1 + l)), 0.f),
                         __ldg(enw2 + l), s);
            smf[EFFW + pp] = 0.85f + 0.13f / (1.f + expf(-(s + b2v)));
            smf[DISTW + pp] = dist;
        }
    }
    __syncthreads();

    // ================= F. stage w2p; merge cv into hjT =====================
    {
        float2* w2p = (float2*)(smf + W2P);
        for (int idx = t; idx < 4096; idx += NT) {
            int kp = idx & 63, n = idx >> 6;
            w2p[kp * 66 + n] = *(const float2*)(fpw2 + n * 128 + 2 * kp);
        }
        for (int idx = t; idx < 4096; idx += NT) {
            int k = idx >> 5, j = idx & 31;
            smf[HJT + k * 33 + j] += smf[CVW + k];
        }
    }
    float b3 = fpb3[0];
    __syncthreads();

    // ================= G. warp-specialized pipelined mainloop ==============
    if (w < 8) {
        // PRODUCER (warps 0-7): h1 build + output fills + pf reduction
        const int pw = w;
        float w1dr[16], hjcvr[16];
#pragma unroll
        for (int s = 0; s < 16; s++) {
            w1dr[s] = smf[W1DW + pw * 16 + s];
            hjcvr[s] = smf[HJT + (pw * 16 + s) * 33 + lane];
        }
        const float4 z4 = make_float4(0.f, 0.f, 0.f, 0.f);
        const float4 o4 = make_float4(1.f, 1.f, 1.f, 1.f);
        float4* outS4 = (float4*)out;
        float4* outE4 = (float4*)(out + MATSZ);
        const int pt = pw * 32 + lane;

        for (int it = 0; it < 8; it++) {
            const int p = it & 1, i0 = 4 * it;
            if (it >= 2) {
                if (p == 0) BSYNC(3); else BSYNC(4);
                if (pw < 4) {
                    float v = 0.f;
#pragma unroll
                    for (int q = 0; q < 8; q++)
                        v += smf[SPARTW + p * 1056 + q * 132 + pw * 33 + lane];
                    float x = v + b3;
                    smf[PFW + (4 * (it - 2) + pw) * 32 + lane] =
                        (x > 20.f) ? x : log1pf(expf(x));
                }
            }
            float dd0 = smf[DISTW + (i0 + 0) * 32 + lane];
            float dd1 = smf[DISTW + (i0 + 1) * 32 + lane];
            float dd2 = smf[DISTW + (i0 + 2) * 32 + lane];
            float dd3 = smf[DISTW + (i0 + 3) * 32 + lane];
            float4* bAB = (float4*)(smf + (p ? BUF1AB : BUF0AB));
            float4* bCD = (float4*)(smf + (p ? BUF1CD : BUF0CD));
#pragma unroll
            for (int sk = 0; sk < 8; sk++) {
                int kp = pw * 8 + sk;
                int l0 = 2 * sk, l1 = l0 + 1;
                int k0 = pw * 16 + l0, k1 = k0 + 1;
                float4 hab, hcd;
                hab.x = fmaxf(smf[HIT + k0 * 33 + i0 + 0] + fmaf(dd0, w1dr[l0], hjcvr[l0]), 0.f);
                hab.y = fmaxf(smf[HIT + k1 * 33 + i0 + 0] + fmaf(dd0, w1dr[l1], hjcvr[l1]), 0.f);
                hab.z = fmaxf(smf[HIT + k0 * 33 + i0 + 1] + fmaf(dd1, w1dr[l0], hjcvr[l0]), 0.f);
                hab.w = fmaxf(smf[HIT + k1 * 33 + i0 + 1] + fmaf(dd1, w1dr[l1], hjcvr[l1]), 0.f);
                hcd.x = fmaxf(smf[HIT + k0 * 33 + i0 + 2] + fmaf(dd2, w1dr[l0], hjcvr[l0]), 0.f);
                hcd.y = fmaxf(smf[HIT + k1 * 33 + i0 + 2] + fmaf(dd2, w1dr[l1], hjcvr[l1]), 0.f);
                hcd.z = fmaxf(smf[HIT + k0 * 33 + i0 + 3] + fmaf(dd3, w1dr[l0], hjcvr[l0]), 0.f);
                hcd.w = fmaxf(smf[HIT + k1 * 33 + i0 + 3] + fmaf(dd3, w1dr[l1], hjcvr[l1]), 0.f);
                bAB[kp * 32 + lane] = hab;
                bCD[kp * 32 + lane] = hcd;
            }
#pragma unroll
            for (int s = 0; s < 4; s++) {
                size_t rb = (size_t)s_gidx[i0 + s] * 1024;
#pragma unroll
                for (int q = 0; q < 4; q++) {
                    outS4[rb + q * 256 + pt] = z4;
                    outE4[rb + q * 256 + pt] = o4;
                }
            }
            if (p == 0) BARRIVE(1); else BARRIVE(2);
        }
        BSYNC(3);
        if (pw < 4) {
            float v = 0.f;
#pragma unroll
            for (int q = 0; q < 8; q++)
                v += smf[SPARTW + q * 132 + pw * 33 + lane];
            float x = v + b3;
            smf[PFW + (24 + pw) * 32 + lane] = (x > 20.f) ? x : log1pf(expf(x));
        }
        BSYNC(4);
        if (pw < 4) {
            float v = 0.f;
#pragma unroll
            for (int q = 0; q < 8; q++)
                v += smf[SPARTW + 1056 + q * 132 + pw * 33 + lane];
            float x = v + b3;
            smf[PFW + (28 + pw) * 32 + lane] = (x > 20.f) ? x : log1pf(expf(x));
        }
    } else {
        // CONSUMER (warps 8-15): n-slice GEMM, j = lane
        const int cw = w - 8;
        const int wb = cw * 4;
        float b2f[8], w3f[8];
#pragma unroll
        for (int q = 0; q < 8; q++) {
            b2f[q] = smf[B2FW + cw * 8 + q];
            w3f[q] = smf[W3FW + cw * 8 + q];
        }
        const ulonglong2* w2u2 = (const ulonglong2*)(smf + W2P);

        for (int it = 0; it < 8; it++) {
            const int p = it & 1;
            if (p == 0) BSYNC(1); else BSYNC(2);
            const ulonglong2* hA = (const ulonglong2*)(smf + (p ? BUF1AB : BUF0AB));
            const ulonglong2* hC = (const ulonglong2*)(smf + (p ? BUF1CD : BUF0CD));
            u64 acc[32];
#pragma unroll
            for (int z = 0; z < 32; z++) acc[z] = 0ull;
#pragma unroll 8
            for (int kp = 0; kp < 64; kp++) {
                ulonglong2 hab = hA[kp * 32 + lane];
                ulonglong2 hcd = hC[kp * 32 + lane];
                ulonglong2 w01 = w2u2[kp * 33 + wb];
                ulonglong2 w23 = w2u2[kp * 33 + wb + 1];
                ulonglong2 w45 = w2u2[kp * 33 + wb + 2];
                ulonglong2 w67 = w2u2[kp * 33 + wb + 3];
                acc[0]  = fma2(hab.x, w01.x, acc[0]);
                acc[1]  = fma2(hab.x, w01.y, acc[1]);
                acc[2]  = fma2(hab.x, w23.x, acc[2]);
                acc[3]  = fma2(hab.x, w23.y, acc[3]);
                acc[4]  = fma2(hab.x, w45.x, acc[4]);
                acc[5]  = fma2(hab.x, w45.y, acc[5]);
                acc[6]  = fma2(hab.x, w67.x, acc[6]);
                acc[7]  = fma2(hab.x, w67.y, acc[7]);
                acc[8]  = fma2(hab.y, w01.x, acc[8]);
                acc[9]  = fma2(hab.y, w01.y, acc[9]);
                acc[10] = fma2(hab.y, w23.x, acc[10]);
                acc[11] = fma2(hab.y, w23.y, acc[11]);
                acc[12] = fma2(hab.y, w45.x, acc[12]);
                acc[13] = fma2(hab.y, w45.y, acc[13]);
                acc[14] = fma2(hab.y, w67.x, acc[14]);
                acc[15] = fma2(hab.y, w67.y, acc[15]);
                acc[16] = fma2(hcd.x, w01.x, acc[16]);
                acc[17] = fma2(hcd.x, w01.y, acc[17]);
                acc[18] = fma2(hcd.x, w23.x, acc[18]);
                acc[19] = fma2(hcd.x, w23.y, acc[19]);
                acc[20] = fma2(hcd.x, w45.x, acc[20]);
                acc[21] = fma2(hcd.x, w45.y, acc[21]);
                acc[22] = fma2(hcd.x, w67.x, acc[22]);
                acc[23] = fma2(hcd.x, w67.y, acc[23]);
                acc[24] = fma2(hcd.y, w01.x, acc[24]);
                acc[25] = fma2(hcd.y, w01.y, acc[25]);
                acc[26] = fma2(hcd.y, w23.x, acc[26]);
                acc[27] = fma2(hcd.y, w23.y, acc[27]);
                acc[28] = fma2(hcd.y, w45.x, acc[28]);
                acc[29] = fma2(hcd.y, w45.y, acc[29]);
                acc[30] = fma2(hcd.y, w67.x, acc[30]);
                acc[31] = fma2(hcd.y, w67.y, acc[31]);
            }
#pragma unroll
            for (int s = 0; s < 4; s++) {
                float v = 0.f;
#pragma unroll
                for (int q = 0; q < 8; q++) {
                    float lo, hi;
                    UNPK2(lo, hi, acc[s * 8 + q]);
                    v = fmaf(fmaxf(lo + hi + b2f[q], 0.f), w3f[q], v);
                }
                smf[SPARTW + p * 1056 + cw * 132 + s * 33 + lane] = v;
            }
            if (p == 0) BARRIVE(3); else BARRIVE(4);
        }
    }
    __syncthreads();

    // ================= H. greedy (warp 0, prefix-scan water-filling) =======
    if (w == 0) {
        float pr = smf[PRIOW + lane];
        int r = 0;
#pragma unroll
        for (int l = 0; l < KC; l++) {
            float q = smf[PRIOW + l];
            r += (q > pr) || (q == pr && l < lane);
        }
        s_ord[r] = lane;
        __syncwarp();
        int oj = s_ord[lane];
        float nets = smf[NETW + oj];
        float dn = nets;
        for (int i = 0; i < 32; i++) {
            int oi = s_ord[i];
            float A = fmaxf(__shfl_sync(0xffffffffu, nets, i), 0.f);
            float needed = -dn;
            float pf = smf[PFW + oi * 32 + oj];
            float cap = (needed > 0.f) ? fminf(needed, pf) : 0.f;
            float C = cap;
#pragma unroll
            for (int o = 1; o < 32; o <<= 1) {
                float x = __shfl_up_sync(0xffffffffu, C, o);
                if (lane >= o) C += x;
            }
            float Cprev = C - cap;
            float avail = A - Cprev;
            bool act = (avail > 0.f) && (needed > 0.f);
            float f = act ? fminf(fminf(avail, needed), pf) : 0.f;
            dn += f * smf[EFFW + oi * 32 + oj];
            smf[FLOWW + i * 32 + lane] = f;
            unsigned ab = __ballot_sync(0xffffffffu, act);
            if (lane == 0) s_actb[i] = ab;
        }
        smf[DNETW + lane] = dn;
        smf[NSRTW + lane] = nets;
    }
    __syncthreads();

    // ================= I. scatter (16 warps x 2 rows) ======================
    {
        float* out_sh = out;
        float* out_ef = out + MATSZ;
        float* out_sent = out + 2 * MATSZ + 1;
        float* out_recv = out_sent + NB;
        float* out_na = out_recv + NB;
        int oj = s_ord[lane];
        int gj = s_gidx[oj];
#pragma unroll
        for (int rr = 0; rr < 2; rr++) {
            int srow = w * 2 + rr;
            int oi = s_ord[srow];
            int gi = s_gidx[oi];
            float f = smf[FLOWW + srow * 32 + lane];
            unsigned ab = s_actb[srow];
            if ((ab >> lane) & 1u) {
                out_sh[(size_t)gi * NB + gj] = f;
                out_ef[(size_t)gi * NB + gj] = smf[EFFW + oi * 32 + oj];
            }
            float v = f;
#pragma unroll
            for (int o = 16; o > 0; o >>= 1) v += __shfl_xor_sync(0xffffffffu, v, o);
            if (lane == 0) {
                out_sent[gi] = v;
                float dnl = smf[DNETW + srow];
                out_recv[gi] = dnl - smf[NSRTW + srow];
                out_na[gi] = dnl;
                smf[RSENTW + srow] = v;
            }
        }
    }
    __syncthreads();

    // ================= J. per-cluster total + last-block global sum ========
    if (t == 0) {
        float tot = 0.f;
#pragma unroll
        for (int i = 0; i < 32; i++) tot += smf[RSENTW + i];
        d_partial[c] = tot;
        __threadfence();
        unsigned old = atomicAdd(&d_ticket, 1u);
        if (old == NC - 1) {
            __threadfence();
            float s0 = 0.f, s1 = 0.f, s2 = 0.f, s3 = 0.f;
#pragma unroll 8
            for (int q = 0; q < NC; q += 4) {
                s0 += __ldcg(d_partial + q);
                s1 += __ldcg(d_partial + q + 1);
                s2 += __ldcg(d_partial + q + 2);
                s3 += __ldcg(d_partial + q + 3);
            }
            out[2 * MATSZ] = (s0 + s1) + (s2 + s3);
            d_ticket = 0;
        }
    }
}

// ------------------------------------------------------------------------------
extern "C" void kernel_launch(void* const* d_in, const int* in_sizes, int n_in,
                              void* d_out, int out_size) {
    const float* emb   = (const float*)d_in[0];
    const float* gen   = (const float*)d_in[1];
    const float* cons  = (const float*)d_in[2];
    const float* pos   = (const float*)d_in[3];
    const float* fpw1  = (const float*)d_in[4];
    const float* fpb1  = (const float*)d_in[5];
    const float* fpw2  = (const float*)d_in[6];
    const float* fpb2  = (const float*)d_in[7];
    const float* fpw3  = (const float*)d_in[8];
    const float* fpb3  = (const float*)d_in[9];
    const float* enw1  = (const float*)d_in[10];
    const float* enb1  = (const float*)d_in[11];
    const float* enw2  = (const float*)d_in[12];
    const float* enb2  = (const float*)d_in[13];
    const float* psw1  = (const float*)d_in[14];
    const float* psb1  = (const float*)d_in[15];
    const float* psw2  = (const float*)d_in[16];
    const float* psb2  = (const float*)d_in[17];
    const int*   assign = (const int*)d_in[18];
    const int*   hour   = (n_in >= 21) ? (const int*)d_in[20] : nullptr;
    float* out = (float*)d_out;

    cudaFuncSetAttribute(mega_kernel,
                         cudaFuncAttributeMaxDynamicSharedMemorySize, SM_BYTES);

    mega_kernel<<<NC, NT, SM_BYTES>>>(emb, gen, cons, pos,
                                      fpw1, fpb1, fpw2, fpb2, fpw3, fpb3,
                                      enw1, enb1, enw2, enb2,
                                      psw1, psb1, psw2, psb2,
                                      assign, hour, out);
}

// round 10
// speedup vs baseline: 1.5787x; 1.0545x over previous
#include <cuda_runtime.h>
#include <math.h>

#define NB 4096
#define NC 128
#define KC 32
#define MATSZ 16777216ULL   // 4096*4096
#define NT 512

__device__ float d_partial[NC];
__device__ unsigned d_ticket;   // zero-init; last block resets

typedef unsigned long long u64;

__device__ __forceinline__ u64 fma2(u64 a, u64 b, u64 c) {
    u64 d;
    asm("fma.rn.f32x2 %0, %1, %2, %3;" : "=l"(d) : "l"(a), "l"(b), "l"(c));
    return d;
}
#define PK2(v, lo, hi)   asm("mov.b64 %0, {%1, %2};" : "=l"(v) : "f"(lo), "f"(hi))
#define UNPK2(lo, hi, v) asm("mov.b64 {%0, %1}, %2;" : "=f"(lo), "=f"(hi) : "l"(v))

#define BSYNC(id)   asm volatile("bar.sync %0, %1;"   :: "n"(id), "n"(NT) : "memory")
#define BARRIVE(id) asm volatile("bar.arrive %0, %1;" :: "n"(id), "n"(NT) : "memory")

// ---- dynamic smem word offsets -------------------------------------------
#define BUF0AB 0
#define BUF0CD 8192
#define BUF1AB 16384
#define BUF1CD 24576
#define W2P    32768
#define HIT    41216
#define HJT    45440
#define DISTW  49664
#define EFFW   50688
#define PFW    51712
#define FLOWW  52736
#define SPARTW 53760
#define W1DW   55872
#define CVW    56000
#define B2FW   56128
#define W3FW   56192
#define GIDX   56256
#define NETW   56288
#define PRIOW  56320
#define ORDW   56352
#define ACTBW  56384
#define DNETW  56416
#define NSRTW  56448
#define RSENTW 56480
#define WCNTW  56512
#define POSW   56528
#define SM_WORDS 56592
#define SM_BYTES (SM_WORDS * 4)
#define EMBT   BUF1AB
// hij w1 staging: stride-260 transposed chunk [kk][cc], 32*260 = 8320 words,
// lives at BUF0AB..(spills into BUF0CD region, free during prologue)
#define W1STRIDE 260

__global__ void __launch_bounds__(NT, 1) mega_kernel(
    const float* __restrict__ emb,  const float* __restrict__ gen,
    const float* __restrict__ cons, const float* __restrict__ pos,
    const float* __restrict__ fpw1, const float* __restrict__ fpb1,
    const float* __restrict__ fpw2, const float* __restrict__ fpb2,
    const float* __restrict__ fpw3, const float* __restrict__ fpb3,
    const float* __restrict__ enw1, const float* __restrict__ enb1,
    const float* __restrict__ enw2, const float* __restrict__ enb2,
    const float* __restrict__ psw1, const float* __restrict__ psb1,
    const float* __restrict__ psw2, const float* __restrict__ psb2,
    const int* __restrict__ assign, const int* __restrict__ hour_p,
    float* __restrict__ out) {
    extern __shared__ float smf[];
    int* s_gidx = (int*)(smf + GIDX);
    int* s_ord  = (int*)(smf + ORDW);
    unsigned* s_actb = (unsigned*)(smf + ACTBW);
    int* s_wcnt = (int*)(smf + WCNTW);
    float2* s_pos2 = (float2*)(smf + POSW);

    const int c = blockIdx.x;
    const int t = threadIdx.x;
    const int w = t >> 5, lane = t & 31;
    const int hour = hour_p ? *hour_p : 12;

    // ================= A. stable grouping (16 warps, 2-pass ballot) ========
    {
        int a[8];
        const int* ap = assign + w * 256;
#pragma unroll
        for (int q = 0; q < 8; q++) a[q] = ap[q * 32 + lane];
        unsigned balls[8];
        int cnt = 0;
#pragma unroll
        for (int q = 0; q < 8; q++) {
            balls[q] = __ballot_sync(0xffffffffu, a[q] == c);
            cnt += __popc(balls[q]);
        }
        if (lane == 0) s_wcnt[w] = cnt;
        __syncthreads();
        int run = 0;
        for (int ww = 0; ww < 16; ww++) if (ww < w) run += s_wcnt[ww];
#pragma unroll
        for (int q = 0; q < 8; q++) {
            if (a[q] == c) {
                int p = run + __popc(balls[q] & ((1u << lane) - 1u));
                if (p < KC) s_gidx[p] = w * 256 + q * 32 + lane;
            }
            run += __popc(balls[q]);
        }
    }
    __syncthreads();

    // ================= B. net, positions, cv/w1d/b2/w3, emb stage ==========
    if (t < KC) {
        int b = s_gidx[t];
        smf[NETW + t] = gen[b * 24 + hour] - cons[b * 24 + hour];
        s_pos2[t] = make_float2(pos[b * 2], pos[b * 2 + 1]);
    }
    {
        float hour_f = (float)hour * (1.f / 24.f);
        if (t >= 256 && t < 384) {
            int k = t - 256;
            smf[W1DW + k] = fpw1[(size_t)k * 258 + 256];
            smf[CVW + k] = fmaf(hour_f, fpw1[(size_t)k * 258 + 257], fpb1[k]);
        }
        if (t >= 384 && t < 448) {
            int n = t - 384;
            smf[B2FW + n] = fpb2[n];
            smf[W3FW + n] = fpw3[n];
        }
        for (int i = t; i < 4096; i += NT) {
            int r = i >> 7, k = i & 127;
            smf[BUF0AB + r * 129 + k] = emb[(size_t)s_gidx[r] * 128 + k];
        }
    }
    __syncthreads();
    for (int i = t; i < 4096; i += NT) {
        int k = i >> 5, r = i & 31;
        smf[EMBT + k * 33 + r] = smf[BUF0AB + r * 129 + k];
    }

    // ================= C. hij GEMM: lane=row, warp covers 16 out-cols ======
    // w1 staging now COALESCED: warp reads along a weight row (lane = k),
    // stores transposed at stride W1STRIDE (multiple of 4 -> aligned LDS.128)
    {
        u64 acc[8];
#pragma unroll
        for (int u = 0; u < 8; u++) acc[u] = 0ull;
        for (int kc = 0; kc < 4; kc++) {
            __syncthreads();
#pragma unroll
            for (int q = 0; q < 16; q++) {
                int cc = q * 16 + w;        // out column 0..255
                float v = (cc < 128)
                    ? fpw1[(size_t)cc * 258 + kc * 32 + lane]
                    : fpw1[(size_t)(cc - 128) * 258 + 128 + kc * 32 + lane];
                smf[BUF0AB + lane * W1STRIDE + cc] = v;
            }
            __syncthreads();
            const u64* w1u = (const u64*)(smf + BUF0AB);
#pragma unroll 4
            for (int kk = 0; kk < 32; kk++) {
                int k = kc * 32 + kk;
                float e = smf[EMBT + k * 33 + lane];
                u64 e2; PK2(e2, e, e);
                const ulonglong2* wr =
                    (const ulonglong2*)(w1u + kk * (W1STRIDE / 2) + w * 8);
                ulonglong2 q0 = wr[0], q1 = wr[1], q2 = wr[2], q3 = wr[3];
                acc[0] = fma2(e2, q0.x, acc[0]);
                acc[1] = fma2(e2, q0.y, acc[1]);
                acc[2] = fma2(e2, q1.x, acc[2]);
                acc[3] = fma2(e2, q1.y, acc[3]);
                acc[4] = fma2(e2, q2.x, acc[4]);
                acc[5] = fma2(e2, q2.y, acc[5]);
                acc[6] = fma2(e2, q3.x, acc[6]);
                acc[7] = fma2(e2, q3.y, acc[7]);
            }
        }
        __syncthreads();
#pragma unroll
        for (int u = 0; u < 8; u++) {
            int pc = w * 8 + u;
            float lo, hi;
            UNPK2(lo, hi, acc[u]);
            if (pc < 64) {
                smf[HIT + (2 * pc) * 33 + lane] = lo;
                smf[HIT + (2 * pc + 1) * 33 + lane] = hi;
            } else {
                smf[HJT + (2 * pc - 128) * 33 + lane] = lo;
                smf[HJT + (2 * pc - 127) * 33 + lane] = hi;
            }
        }
    }
    __syncthreads();

    // ================= D. priority MLP (16 warps x 2 rows) =================
    {
        float* s_pT = smf + BUF0AB;
        for (int i = t; i < 4096; i += NT) {
            int m = i >> 7, e = i & 127;
            s_pT[e * 33 + m] = psw1[i];
        }
        __syncthreads();
        float b1m = psb1[lane], w2m = psw2[lane], b2s = psb2[0];
#pragma unroll
        for (int rr = 0; rr < 2; rr++) {
            int r = w * 2 + rr;
            float acc = b1m;
#pragma unroll 8
            for (int e = 0; e < 128; e++)
                acc = fmaf(smf[EMBT + e * 33 + r], s_pT[e * 33 + lane], acc);
            float v = fmaxf(acc, 0.f) * w2m;
#pragma unroll
            for (int o = 16; o > 0; o >>= 1) v += __shfl_xor_sync(0xffffffffu, v, o);
            if (lane == 0) smf[PRIOW + r] = 1.f / (1.f + expf(-(v + b2s)));
        }
    }

    // ================= E. dist + efficiency ================================
    {
        float b2v = enb2[0];
        for (int pp = t; pp < 1024; pp += NT) {
            int i = pp >> 5, j = pp & 31;
            float2 pi = s_pos2[i], pj = s_pos2[j];
            float dx = pi.x - pj.x, dy = pi.y - pj.y;
            float dist = sqrtf(dx * dx + dy * dy);
            float tq = dist * (1.f / 1000.f);
            float s = 0.f;
#pragma unroll
            for (int l = 0; l < 16; l++)
                s = fmaf(fmaxf(fmaf(tq, __ldg(enw1 + l), __ldg(enb1 + l)), 0.f),
                         __ldg(enw2 + l), s);
            smf[EFFW + pp] = 0.85f + 0.13f / (1.f + expf(-(s + b2v)));
            smf[DISTW + pp] = dist;
        }
    }
    __syncthreads();

    // ================= F. stage w2p; merge cv into hjT =====================
    {
        float2* w2p = (float2*)(smf + W2P);
        for (int idx = t; idx < 4096; idx += NT) {
            int kp = idx & 63, n = idx >> 6;
            w2p[kp * 66 + n] = *(const float2*)(fpw2 + n * 128 + 2 * kp);
        }
        for (int idx = t; idx < 4096; idx += NT) {
            int k = idx >> 5, j = idx & 31;
            smf[HJT + k * 33 + j] += smf[CVW + k];
        }
    }
    float b3 = fpb3[0];
    __syncthreads();

    // ================= G. warp-specialized pipelined mainloop ==============
    if (w < 8) {
        // PRODUCER (warps 0-7): h1 build + output fills + pf reduction
        const int pw = w;
        float w1dr[16], hjcvr[16];
#pragma unroll
        for (int s = 0; s < 16; s++) {
            w1dr[s] = smf[W1DW + pw * 16 + s];
            hjcvr[s] = smf[HJT + (pw * 16 + s) * 33 + lane];
        }
        const float4 z4 = make_float4(0.f, 0.f, 0.f, 0.f);
        const float4 o4 = make_float4(1.f, 1.f, 1.f, 1.f);
        float4* outS4 = (float4*)out;
        float4* outE4 = (float4*)(out + MATSZ);
        const int pt = pw * 32 + lane;

        for (int it = 0; it < 8; it++) {
            const int p = it & 1, i0 = 4 * it;
            if (it >= 2) {
                if (p == 0) BSYNC(3); else BSYNC(4);
                if (pw < 4) {
                    float v = 0.f;
#pragma unroll
                    for (int q = 0; q < 8; q++)
                        v += smf[SPARTW + p * 1056 + q * 132 + pw * 33 + lane];
                    float x = v + b3;
                    smf[PFW + (4 * (it - 2) + pw) * 32 + lane] =
                        (x > 20.f) ? x : log1pf(expf(x));
                }
            }
            float dd0 = smf[DISTW + (i0 + 0) * 32 + lane];
            float dd1 = smf[DISTW + (i0 + 1) * 32 + lane];
            float dd2 = smf[DISTW + (i0 + 2) * 32 + lane];
            float dd3 = smf[DISTW + (i0 + 3) * 32 + lane];
            float4* bAB = (float4*)(smf + (p ? BUF1AB : BUF0AB));
            float4* bCD = (float4*)(smf + (p ? BUF1CD : BUF0CD));
#pragma unroll
            for (int sk = 0; sk < 8; sk++) {
                int kp = pw * 8 + sk;
                int l0 = 2 * sk, l1 = l0 + 1;
                int k0 = pw * 16 + l0, k1 = k0 + 1;
                float4 hab, hcd;
                hab.x = fmaxf(smf[HIT + k0 * 33 + i0 + 0] + fmaf(dd0, w1dr[l0], hjcvr[l0]), 0.f);
                hab.y = fmaxf(smf[HIT + k1 * 33 + i0 + 0] + fmaf(dd0, w1dr[l1], hjcvr[l1]), 0.f);
                hab.z = fmaxf(smf[HIT + k0 * 33 + i0 + 1] + fmaf(dd1, w1dr[l0], hjcvr[l0]), 0.f);
                hab.w = fmaxf(smf[HIT + k1 * 33 + i0 + 1] + fmaf(dd1, w1dr[l1], hjcvr[l1]), 0.f);
                hcd.x = fmaxf(smf[HIT + k0 * 33 + i0 + 2] + fmaf(dd2, w1dr[l0], hjcvr[l0]), 0.f);
                hcd.y = fmaxf(smf[HIT + k1 * 33 + i0 + 2] + fmaf(dd2, w1dr[l1], hjcvr[l1]), 0.f);
                hcd.z = fmaxf(smf[HIT + k0 * 33 + i0 + 3] + fmaf(dd3, w1dr[l0], hjcvr[l0]), 0.f);
                hcd.w = fmaxf(smf[HIT + k1 * 33 + i0 + 3] + fmaf(dd3, w1dr[l1], hjcvr[l1]), 0.f);
                bAB[kp * 32 + lane] = hab;
                bCD[kp * 32 + lane] = hcd;
            }
#pragma unroll
            for (int s = 0; s < 4; s++) {
                size_t rb = (size_t)s_gidx[i0 + s] * 1024;
#pragma unroll
                for (int q = 0; q < 4; q++) {
                    outS4[rb + q * 256 + pt] = z4;
                    outE4[rb + q * 256 + pt] = o4;
                }
            }
            if (p == 0) BARRIVE(1); else BARRIVE(2);
        }
        BSYNC(3);
        if (pw < 4) {
            float v = 0.f;
#pragma unroll
            for (int q = 0; q < 8; q++)
                v += smf[SPARTW + q * 132 + pw * 33 + lane];
            float x = v + b3;
            smf[PFW + (24 + pw) * 32 + lane] = (x > 20.f) ? x : log1pf(expf(x));
        }
        BSYNC(4);
        if (pw < 4) {
            float v = 0.f;
#pragma unroll
            for (int q = 0; q < 8; q++)
                v += smf[SPARTW + 1056 + q * 132 + pw * 33 + lane];
            float x = v + b3;
            smf[PFW + (28 + pw) * 32 + lane] = (x > 20.f) ? x : log1pf(expf(x));
        }
    } else {
        // CONSUMER (warps 8-15): n-slice GEMM, j = lane
        const int cw = w - 8;
        const int wb = cw * 4;
        float b2f[8], w3f[8];
#pragma unroll
        for (int q = 0; q < 8; q++) {
            b2f[q] = smf[B2FW + cw * 8 + q];
            w3f[q] = smf[W3FW + cw * 8 + q];
        }
        const ulonglong2* w2u2 = (const ulonglong2*)(smf + W2P);

        for (int it = 0; it < 8; it++) {
            const int p = it & 1;
            if (p == 0) BSYNC(1); else BSYNC(2);
            const ulonglong2* hA = (const ulonglong2*)(smf + (p ? BUF1AB : BUF0AB));
            const ulonglong2* hC = (const ulonglong2*)(smf + (p ? BUF1CD : BUF0CD));
            u64 acc[32];
#pragma unroll
            for (int z = 0; z < 32; z++) acc[z] = 0ull;
#pragma unroll 8
            for (int kp = 0; kp < 64; kp++) {
                ulonglong2 hab = hA[kp * 32 + lane];
                ulonglong2 hcd = hC[kp * 32 + lane];
                ulonglong2 w01 = w2u2[kp * 33 + wb];
                ulonglong2 w23 = w2u2[kp * 33 + wb + 1];
                ulonglong2 w45 = w2u2[kp * 33 + wb + 2];
                ulonglong2 w67 = w2u2[kp * 33 + wb + 3];
                acc[0]  = fma2(hab.x, w01.x, acc[0]);
                acc[1]  = fma2(hab.x, w01.y, acc[1]);
                acc[2]  = fma2(hab.x, w23.x, acc[2]);
                acc[3]  = fma2(hab.x, w23.y, acc[3]);
                acc[4]  = fma2(hab.x, w45.x, acc[4]);
                acc[5]  = fma2(hab.x, w45.y, acc[5]);
                acc[6]  = fma2(hab.x, w67.x, acc[6]);
                acc[7]  = fma2(hab.x, w67.y, acc[7]);
                acc[8]  = fma2(hab.y, w01.x, acc[8]);
                acc[9]  = fma2(hab.y, w01.y, acc[9]);
                acc[10] = fma2(hab.y, w23.x, acc[10]);
                acc[11] = fma2(hab.y, w23.y, acc[11]);
                acc[12] = fma2(hab.y, w45.x, acc[12]);
                acc[13] = fma2(hab.y, w45.y, acc[13]);
                acc[14] = fma2(hab.y, w67.x, acc[14]);
                acc[15] = fma2(hab.y, w67.y, acc[15]);
                acc[16] = fma2(hcd.x, w01.x, acc[16]);
                acc[17] = fma2(hcd.x, w01.y, acc[17]);
                acc[18] = fma2(hcd.x, w23.x, acc[18]);
                acc[19] = fma2(hcd.x, w23.y, acc[19]);
                acc[20] = fma2(hcd.x, w45.x, acc[20]);
                acc[21] = fma2(hcd.x, w45.y, acc[21]);
                acc[22] = fma2(hcd.x, w67.x, acc[22]);
                acc[23] = fma2(hcd.x, w67.y, acc[23]);
                acc[24] = fma2(hcd.y, w01.x, acc[24]);
                acc[25] = fma2(hcd.y, w01.y, acc[25]);
                acc[26] = fma2(hcd.y, w23.x, acc[26]);
                acc[27] = fma2(hcd.y, w23.y, acc[27]);
                acc[28] = fma2(hcd.y, w45.x, acc[28]);
                acc[29] = fma2(hcd.y, w45.y, acc[29]);
                acc[30] = fma2(hcd.y, w67.x, acc[30]);
                acc[31] = fma2(hcd.y, w67.y, acc[31]);
            }
#pragma unroll
            for (int s = 0; s < 4; s++) {
                float v = 0.f;
#pragma unroll
                for (int q = 0; q < 8; q++) {
                    float lo, hi;
                    UNPK2(lo, hi, acc[s * 8 + q]);
                    v = fmaf(fmaxf(lo + hi + b2f[q], 0.f), w3f[q], v);
                }
                smf[SPARTW + p * 1056 + cw * 132 + s * 33 + lane] = v;
            }
            if (p == 0) BARRIVE(3); else BARRIVE(4);
        }
    }
    __syncthreads();

    // ================= H. greedy (warp 0, prefix-scan water-filling) =======
    if (w == 0) {
        float pr = smf[PRIOW + lane];
        int r = 0;
#pragma unroll
        for (int l = 0; l < KC; l++) {
            float q = smf[PRIOW + l];
            r += (q > pr) || (q == pr && l < lane);
        }
        s_ord[r] = lane;
        __syncwarp();
        int oj = s_ord[lane];
        float nets = smf[NETW + oj];
        float dn = nets;
        for (int i = 0; i < 32; i++) {
            int oi = s_ord[i];
            float A = fmaxf(__shfl_sync(0xffffffffu, nets, i), 0.f);
            float needed = -dn;
            float pf = smf[PFW + oi * 32 + oj];
            float cap = (needed > 0.f) ? fminf(needed, pf) : 0.f;
            float C = cap;
#pragma unroll
            for (int o = 1; o < 32; o <<= 1) {
                float x = __shfl_up_sync(0xffffffffu, C, o);
                if (lane >= o) C += x;
            }
            float Cprev = C - cap;
            float avail = A - Cprev;
            bool act = (avail > 0.f) && (needed > 0.f);
            float f = act ? fminf(fminf(avail, needed), pf) : 0.f;
            dn += f * smf[EFFW + oi * 32 + oj];
            smf[FLOWW + i * 32 + lane] = f;
            unsigned ab = __ballot_sync(0xffffffffu, act);
            if (lane == 0) s_actb[i] = ab;
        }
        smf[DNETW + lane] = dn;
        smf[NSRTW + lane] = nets;
    }
    __syncthreads();

    // ================= I. scatter (16 warps x 2 rows) ======================
    {
        float* out_sh = out;
        float* out_ef = out + MATSZ;
        float* out_sent = out + 2 * MATSZ + 1;
        float* out_recv = out_sent + NB;
        float* out_na = out_recv + NB;
        int oj = s_ord[lane];
        int gj = s_gidx[oj];
#pragma unroll
        for (int rr = 0; rr < 2; rr++) {
            int srow = w * 2 + rr;
            int oi = s_ord[srow];
            int gi = s_gidx[oi];
            float f = smf[FLOWW + srow * 32 + lane];
            unsigned ab = s_actb[srow];
            if ((ab >> lane) & 1u) {
                out_sh[(size_t)gi * NB + gj] = f;
                out_ef[(size_t)gi * NB + gj] = smf[EFFW + oi * 32 + oj];
            }
            float v = f;
#pragma unroll
            for (int o = 16; o > 0; o >>= 1) v += __shfl_xor_sync(0xffffffffu, v, o);
            if (lane == 0) {
                out_sent[gi] = v;
                float dnl = smf[DNETW + srow];
                out_recv[gi] = dnl - smf[NSRTW + srow];
                out_na[gi] = dnl;
                smf[RSENTW + srow] = v;
            }
        }
    }
    __syncthreads();

    // ================= J. per-cluster total + last-block global sum ========
    if (t == 0) {
        float tot = 0.f;
#pragma unroll
        for (int i = 0; i < 32; i++) tot += smf[RSENTW + i];
        d_partial[c] = tot;
        __threadfence();
        unsigned old = atomicAdd(&d_ticket, 1u);
        if (old == NC - 1) {
            __threadfence();
            float s0 = 0.f, s1 = 0.f, s2 = 0.f, s3 = 0.f;
#pragma unroll 8
            for (int q = 0; q < NC; q += 4) {
                s0 += __ldcg(d_partial + q);
                s1 += __ldcg(d_partial + q + 1);
                s2 += __ldcg(d_partial + q + 2);
                s3 += __ldcg(d_partial + q + 3);
            }
            out[2 * MATSZ] = (s0 + s1) + (s2 + s3);
            d_ticket = 0;
        }
    }
}

// ------------------------------------------------------------------------------
extern "C" void kernel_launch(void* const* d_in, const int* in_sizes, int n_in,
                              void* d_out, int out_size) {
    const float* emb   = (const float*)d_in[0];
    const float* gen   = (const float*)d_in[1];
    const float* cons  = (const float*)d_in[2];
    const float* pos   = (const float*)d_in[3];
    const float* fpw1  = (const float*)d_in[4];
    const float* fpb1  = (const float*)d_in[5];
    const float* fpw2  = (const float*)d_in[6];
    const float* fpb2  = (const float*)d_in[7];
    const float* fpw3  = (const float*)d_in[8];
    const float* fpb3  = (const float*)d_in[9];
    const float* enw1  = (const float*)d_in[10];
    const float* enb1  = (const float*)d_in[11];
    const float* enw2  = (const float*)d_in[12];
    const float* enb2  = (const float*)d_in[13];
    const float* psw1  = (const float*)d_in[14];
    const float* psb1  = (const float*)d_in[15];
    const float* psw2  = (const float*)d_in[16];
    const float* psb2  = (const float*)d_in[17];
    const int*   assign = (const int*)d_in[18];
    const int*   hour   = (n_in >= 21) ? (const int*)d_in[20] : nullptr;
    float* out = (float*)d_out;

    cudaFuncSetAttribute(mega_kernel,
                         cudaFuncAttributeMaxDynamicSharedMemorySize, SM_BYTES);

    mega_kernel<<<NC, NT, SM_BYTES>>>(emb, gen, cons, pos,
                                      fpw1, fpb1, fpw2, fpb2, fpw3, fpb3,
                                      enw1, enb1, enw2, enb2,
                                      psw1, psb1, psw2, psb2,
                                      assign, hour, out);
}

// round 11
// speedup vs baseline: 2.1675x; 1.3729x over previous
#include <cuda_runtime.h>
#include <math.h>
#include <stdint.h>

#define NB 4096
#define NC 128
#define KC 32
#define MATSZ 16777216ULL   // 4096*4096
#define NT 512

__device__ float d_partial[NC];
__device__ unsigned d_ticket;   // zero-init; last block resets

typedef unsigned long long u64;

__device__ __forceinline__ u64 fma2(u64 a, u64 b, u64 c) {
    u64 d;
    asm("fma.rn.f32x2 %0, %1, %2, %3;" : "=l"(d) : "l"(a), "l"(b), "l"(c));
    return d;
}
#define PK2(v, lo, hi)   asm("mov.b64 %0, {%1, %2};" : "=l"(v) : "f"(lo), "f"(hi))
#define UNPK2(lo, hi, v) asm("mov.b64 {%0, %1}, %2;" : "=f"(lo), "=f"(hi) : "l"(v))

__device__ __forceinline__ uint32_t f2tf(float f) {
    uint32_t r;
    asm("cvt.rna.tf32.f32 %0, %1;" : "=r"(r) : "f"(f));
    return r;
}
#define MMA_TF32(d0, d1, d2, d3, a0, a1, a2, a3, b0, b1) \
    asm volatile("mma.sync.aligned.m16n8k8.row.col.f32.tf32.tf32.f32 " \
                 "{%0,%1,%2,%3}, {%4,%5,%6,%7}, {%8,%9}, {%0,%1,%2,%3};" \
                 : "+f"(d0), "+f"(d1), "+f"(d2), "+f"(d3) \
                 : "r"(a0), "r"(a1), "r"(a2), "r"(a3), "r"(b0), "r"(b1))

#define BSYNC(id)   asm volatile("bar.sync %0, %1;"   :: "n"(id), "n"(NT) : "memory")
#define BARRIVE(id) asm volatile("bar.arrive %0, %1;" :: "n"(id), "n"(NT) : "memory")

// ---- dynamic smem word offsets -------------------------------------------
#define ABUF0  0        // 16896 w: h1 tile [row 0..127][k stride 132] tf32 bits
#define ABUF1  16896    // 16896 w: parity 1
#define W2FRAG 33792    // 8192 w: B fragments [(tp*8+nt)*32+lane] uint4
#define HIT    41984    // 4224 w  hiT[k*33 + i]
#define HJT    46208    // 4224 w  hjT[k*33 + j] (cv merged)
#define DISTW  50432    // 1024
#define EFFW   51456    // 1024
#define PFW    52480    // 1024
#define FLOWW  53504    // 1024
#define W1DW   54528    // 128
#define CVW    54656    // 128
#define B2FW   54784    // 64
#define W3FW   54848    // 64
#define GIDX   54912    // int[32]
#define NETW   54944
#define PRIOW  54976
#define ORDW   55008
#define ACTBW  55040
#define DNETW  55072
#define NSRTW  55104
#define RSENTW 55136
#define WCNTW  55168    // int[16]
#define POSW   55184    // float2[32] = 64 w
#define SM_WORDS 55248
#define SM_BYTES (SM_WORDS * 4)
// prologue overlays: emb row-stage (stride129) / w1 staging / psw1T in ABUF0;
// EMBT (stride33, 4224 w) in ABUF1
#define EMBT   ABUF1
#define W1STRIDE 260

__global__ void __launch_bounds__(NT, 1) mega_kernel(
    const float* __restrict__ emb,  const float* __restrict__ gen,
    const float* __restrict__ cons, const float* __restrict__ pos,
    const float* __restrict__ fpw1, const float* __restrict__ fpb1,
    const float* __restrict__ fpw2, const float* __restrict__ fpb2,
    const float* __restrict__ fpw3, const float* __restrict__ fpb3,
    const float* __restrict__ enw1, const float* __restrict__ enb1,
    const float* __restrict__ enw2, const float* __restrict__ enb2,
    const float* __restrict__ psw1, const float* __restrict__ psb1,
    const float* __restrict__ psw2, const float* __restrict__ psb2,
    const int* __restrict__ assign, const int* __restrict__ hour_p,
    float* __restrict__ out) {
    extern __shared__ float smf[];
    int* s_gidx = (int*)(smf + GIDX);
    int* s_ord  = (int*)(smf + ORDW);
    unsigned* s_actb = (unsigned*)(smf + ACTBW);
    int* s_wcnt = (int*)(smf + WCNTW);
    float2* s_pos2 = (float2*)(smf + POSW);

    const int c = blockIdx.x;
    const int t = threadIdx.x;
    const int w = t >> 5, lane = t & 31;
    const int hour = hour_p ? *hour_p : 12;

    // ================= A. stable grouping (16 warps, 2-pass ballot) ========
    {
        int a[8];
        const int* ap = assign + w * 256;
#pragma unroll
        for (int q = 0; q < 8; q++) a[q] = ap[q * 32 + lane];
        unsigned balls[8];
        int cnt = 0;
#pragma unroll
        for (int q = 0; q < 8; q++) {
            balls[q] = __ballot_sync(0xffffffffu, a[q] == c);
            cnt += __popc(balls[q]);
        }
        if (lane == 0) s_wcnt[w] = cnt;
        __syncthreads();
        int run = 0;
        for (int ww = 0; ww < 16; ww++) if (ww < w) run += s_wcnt[ww];
#pragma unroll
        for (int q = 0; q < 8; q++) {
            if (a[q] == c) {
                int p = run + __popc(balls[q] & ((1u << lane) - 1u));
                if (p < KC) s_gidx[p] = w * 256 + q * 32 + lane;
            }
            run += __popc(balls[q]);
        }
    }
    __syncthreads();

    // ================= B. net, positions, cv/w1d/b2/w3, emb stage ==========
    if (t < KC) {
        int b = s_gidx[t];
        smf[NETW + t] = gen[b * 24 + hour] - cons[b * 24 + hour];
        s_pos2[t] = make_float2(pos[b * 2], pos[b * 2 + 1]);
    }
    {
        float hour_f = (float)hour * (1.f / 24.f);
        if (t >= 256 && t < 384) {
            int k = t - 256;
            smf[W1DW + k] = fpw1[(size_t)k * 258 + 256];
            smf[CVW + k] = fmaf(hour_f, fpw1[(size_t)k * 258 + 257], fpb1[k]);
        }
        if (t >= 384 && t < 448) {
            int n = t - 384;
            smf[B2FW + n] = fpb2[n];
            smf[W3FW + n] = fpw3[n];
        }
        for (int i = t; i < 4096; i += NT) {
            int r = i >> 7, k = i & 127;
            smf[ABUF0 + r * 129 + k] = emb[(size_t)s_gidx[r] * 128 + k];
        }
    }
    __syncthreads();
    for (int i = t; i < 4096; i += NT) {
        int k = i >> 5, r = i & 31;
        smf[EMBT + k * 33 + r] = smf[ABUF0 + r * 129 + k];
    }

    // ================= C. hij GEMM: lane=row, warp covers 16 out-cols ======
    {
        u64 acc[8];
#pragma unroll
        for (int u = 0; u < 8; u++) acc[u] = 0ull;
        for (int kc = 0; kc < 4; kc++) {
            __syncthreads();
#pragma unroll
            for (int q = 0; q < 16; q++) {
                int cc = q * 16 + w;        // out column 0..255
                float v = (cc < 128)
                    ? fpw1[(size_t)cc * 258 + kc * 32 + lane]
                    : fpw1[(size_t)(cc - 128) * 258 + 128 + kc * 32 + lane];
                smf[ABUF0 + lane * W1STRIDE + cc] = v;
            }
            __syncthreads();
            const u64* w1u = (const u64*)(smf + ABUF0);
#pragma unroll 4
            for (int kk = 0; kk < 32; kk++) {
                int k = kc * 32 + kk;
                float e = smf[EMBT + k * 33 + lane];
                u64 e2; PK2(e2, e, e);
                const ulonglong2* wr =
                    (const ulonglong2*)(w1u + kk * (W1STRIDE / 2) + w * 8);
                ulonglong2 q0 = wr[0], q1 = wr[1], q2 = wr[2], q3 = wr[3];
                acc[0] = fma2(e2, q0.x, acc[0]);
                acc[1] = fma2(e2, q0.y, acc[1]);
                acc[2] = fma2(e2, q1.x, acc[2]);
                acc[3] = fma2(e2, q1.y, acc[3]);
                acc[4] = fma2(e2, q2.x, acc[4]);
                acc[5] = fma2(e2, q2.y, acc[5]);
                acc[6] = fma2(e2, q3.x, acc[6]);
                acc[7] = fma2(e2, q3.y, acc[7]);
            }
        }
        __syncthreads();
#pragma unroll
        for (int u = 0; u < 8; u++) {
            int pc = w * 8 + u;
            float lo, hi;
            UNPK2(lo, hi, acc[u]);
            if (pc < 64) {
                smf[HIT + (2 * pc) * 33 + lane] = lo;
                smf[HIT + (2 * pc + 1) * 33 + lane] = hi;
            } else {
                smf[HJT + (2 * pc - 128) * 33 + lane] = lo;
                smf[HJT + (2 * pc - 127) * 33 + lane] = hi;
            }
        }
    }
    __syncthreads();

    // ================= D. priority MLP (16 warps x 2 rows) =================
    {
        float* s_pT = smf + ABUF0;
        for (int i = t; i < 4096; i += NT) {
            int m = i >> 7, e = i & 127;
            s_pT[e * 33 + m] = psw1[i];
        }
        __syncthreads();
        float b1m = psb1[lane], w2m = psw2[lane], b2s = psb2[0];
#pragma unroll
        for (int rr = 0; rr < 2; rr++) {
            int r = w * 2 + rr;
            float acc = b1m;
#pragma unroll 8
            for (int e = 0; e < 128; e++)
                acc = fmaf(smf[EMBT + e * 33 + r], s_pT[e * 33 + lane], acc);
            float v = fmaxf(acc, 0.f) * w2m;
#pragma unroll
            for (int o = 16; o > 0; o >>= 1) v += __shfl_xor_sync(0xffffffffu, v, o);
            if (lane == 0) smf[PRIOW + r] = 1.f / (1.f + expf(-(v + b2s)));
        }
    }

    // ================= E. dist + efficiency ================================
    {
        float b2v = enb2[0];
        for (int pp = t; pp < 1024; pp += NT) {
            int i = pp >> 5, j = pp & 31;
            float2 pi = s_pos2[i], pj = s_pos2[j];
            float dx = pi.x - pj.x, dy = pi.y - pj.y;
            float dist = sqrtf(dx * dx + dy * dy);
            float tq = dist * (1.f / 1000.f);
            float s = 0.f;
#pragma unroll
            for (int l = 0; l < 16; l++)
                s = fmaf(fmaxf(fmaf(tq, __ldg(enw1 + l), __ldg(enb1 + l)), 0.f),
                         __ldg(enw2 + l), s);
            smf[EFFW + pp] = 0.85f + 0.13f / (1.f + expf(-(s + b2v)));
            smf[DISTW + pp] = dist;
        }
    }
    __syncthreads();

    // ================= F. stage w2 B-fragments (tf32); merge cv into hjT ===
    {
        uint4* bf = (uint4*)(smf + W2FRAG);
        for (int idx = t; idx < 2048; idx += NT) {
            int tp = idx >> 8;               // ktile-pair 0..7
            int rem = idx & 255;
            int nt = rem >> 5, l2 = rem & 31;
            int n = nt * 8 + (l2 >> 2);
            int kb = tp * 16 + (l2 & 3);
            const float* wrow = fpw2 + n * 128 + kb;
            uint4 v;
            v.x = f2tf(__ldg(wrow));         // b0 of ktile 2tp   (k = kb)
            v.y = f2tf(__ldg(wrow + 4));     // b1 of ktile 2tp   (k = kb+4)
            v.z = f2tf(__ldg(wrow + 8));     // b0 of ktile 2tp+1 (k = kb+8)
            v.w = f2tf(__ldg(wrow + 12));    // b1 of ktile 2tp+1 (k = kb+12)
            bf[idx] = v;
        }
        for (int idx = t; idx < 4096; idx += NT) {
            int k = idx >> 5, j = idx & 31;
            smf[HJT + k * 33 + j] += smf[CVW + k];
        }
    }
    float b3 = fpb3[0];
    __syncthreads();

    // ================= G. warp-specialized tensor-core mainloop ============
    if (w < 8) {
        // PRODUCER (warps 0-7): h1 (tf32, stride-132 tile) + output fills
        const int pw = w;
        float w1dr[16], hjcvr[16];
#pragma unroll
        for (int s = 0; s < 16; s++) {
            w1dr[s] = smf[W1DW + pw * 16 + s];
            hjcvr[s] = smf[HJT + (pw * 16 + s) * 33 + lane];
        }
        const float4 z4 = make_float4(0.f, 0.f, 0.f, 0.f);
        const float4 o4 = make_float4(1.f, 1.f, 1.f, 1.f);
        float4* outS4 = (float4*)out;
        float4* outE4 = (float4*)(out + MATSZ);
        const int pt = pw * 32 + lane;

        for (int it = 0; it < 8; it++) {
            const int p = it & 1, i0 = 4 * it;
            if (it >= 2) { if (p == 0) BSYNC(3); else BSYNC(4); }
            uint32_t* bufw = (uint32_t*)(smf + (p ? ABUF1 : ABUF0));
#pragma unroll
            for (int sid = 0; sid < 4; sid++) {
                int row = sid * 32 + lane;
                float dd = smf[DISTW + (i0 + sid) * 32 + lane];
#pragma unroll
                for (int g = 0; g < 4; g++) {
                    int l0 = g * 4;
                    int k0 = pw * 16 + l0;
                    uint4 hv;
                    hv.x = f2tf(fmaxf(smf[HIT + (k0 + 0) * 33 + i0 + sid]
                                      + fmaf(dd, w1dr[l0 + 0], hjcvr[l0 + 0]), 0.f));
                    hv.y = f2tf(fmaxf(smf[HIT + (k0 + 1) * 33 + i0 + sid]
                                      + fmaf(dd, w1dr[l0 + 1], hjcvr[l0 + 1]), 0.f));
                    hv.z = f2tf(fmaxf(smf[HIT + (k0 + 2) * 33 + i0 + sid]
                                      + fmaf(dd, w1dr[l0 + 2], hjcvr[l0 + 2]), 0.f));
                    hv.w = f2tf(fmaxf(smf[HIT + (k0 + 3) * 33 + i0 + sid]
                                      + fmaf(dd, w1dr[l0 + 3], hjcvr[l0 + 3]), 0.f));
                    *(uint4*)(bufw + row * 132 + k0) = hv;
                }
            }
#pragma unroll
            for (int s = 0; s < 4; s++) {
                size_t rb = (size_t)s_gidx[i0 + s] * 1024;
#pragma unroll
                for (int q = 0; q < 4; q++) {
                    outS4[rb + q * 256 + pt] = z4;
                    outE4[rb + q * 256 + pt] = o4;
                }
            }
            if (p == 0) BARRIVE(1); else BARRIVE(2);
        }
    } else {
        // CONSUMER (warps 8-15): tf32 mma.sync, 16-row strip x 64 n
        const int cw = w - 8;
        const int g = lane >> 2, l4 = lane & 3;
        const int rl = (cw * 16 + g) * 132;
        const int rh = rl + 8 * 132;
        const uint4* bfrag = (const uint4*)(smf + W2FRAG);

        for (int it = 0; it < 8; it++) {
            const int p = it & 1, i0 = 4 * it;
            if (p == 0) BSYNC(1); else BSYNC(2);
            const uint32_t* h1u = (const uint32_t*)(smf + (p ? ABUF1 : ABUF0));
            float acc[8][4];
#pragma unroll
            for (int nt = 0; nt < 8; nt++) {
                acc[nt][0] = 0.f; acc[nt][1] = 0.f;
                acc[nt][2] = 0.f; acc[nt][3] = 0.f;
            }
#pragma unroll
            for (int tp = 0; tp < 8; tp++) {
                int kb = tp * 16 + l4;
                uint32_t a0 = h1u[rl + kb],      a1 = h1u[rh + kb];
                uint32_t a2 = h1u[rl + kb + 4],  a3 = h1u[rh + kb + 4];
                uint32_t a4 = h1u[rl + kb + 8],  a5 = h1u[rh + kb + 8];
                uint32_t a6 = h1u[rl + kb + 12], a7 = h1u[rh + kb + 12];
                const uint4* bp = bfrag + tp * 256 + lane;
#pragma unroll
                for (int nt = 0; nt < 8; nt++) {
                    uint4 bv = bp[nt * 32];
                    MMA_TF32(acc[nt][0], acc[nt][1], acc[nt][2], acc[nt][3],
                             a0, a1, a2, a3, bv.x, bv.y);
                    MMA_TF32(acc[nt][0], acc[nt][1], acc[nt][2], acc[nt][3],
                             a4, a5, a6, a7, bv.z, bv.w);
                }
            }
            // epilogue: relu(+b2) dot w3 over 64 n, quad reduce, softplus
            float vlo = 0.f, vhi = 0.f;
#pragma unroll
            for (int nt = 0; nt < 8; nt++) {
                int n0 = nt * 8 + 2 * l4;
                float b2a = smf[B2FW + n0], b2b = smf[B2FW + n0 + 1];
                float w3a = smf[W3FW + n0], w3b = smf[W3FW + n0 + 1];
                vlo = fmaf(fmaxf(acc[nt][0] + b2a, 0.f), w3a, vlo);
                vlo = fmaf(fmaxf(acc[nt][1] + b2b, 0.f), w3b, vlo);
                vhi = fmaf(fmaxf(acc[nt][2] + b2a, 0.f), w3a, vhi);
                vhi = fmaf(fmaxf(acc[nt][3] + b2b, 0.f), w3b, vhi);
            }
            vlo += __shfl_xor_sync(0xffffffffu, vlo, 1);
            vlo += __shfl_xor_sync(0xffffffffu, vlo, 2);
            vhi += __shfl_xor_sync(0xffffffffu, vhi, 1);
            vhi += __shfl_xor_sync(0xffffffffu, vhi, 2);
            if (l4 == 0) {
                int r0 = cw * 16 + g;
                float x = vlo + b3;
                smf[PFW + (i0 + (r0 >> 5)) * 32 + (r0 & 31)] =
                    (x > 20.f) ? x : log1pf(expf(x));
                int r1 = r0 + 8;
                x = vhi + b3;
                smf[PFW + (i0 + (r1 >> 5)) * 32 + (r1 & 31)] =
                    (x > 20.f) ? x : log1pf(expf(x));
            }
            if (p == 0) BARRIVE(3); else BARRIVE(4);
        }
    }
    __syncthreads();

    // ================= H. greedy (warp 0, prefix-scan water-filling) =======
    if (w == 0) {
        float pr = smf[PRIOW + lane];
        int r = 0;
#pragma unroll
        for (int l = 0; l < KC; l++) {
            float q = smf[PRIOW + l];
            r += (q > pr) || (q == pr && l < lane);
        }
        s_ord[r] = lane;
        __syncwarp();
        int oj = s_ord[lane];
        float nets = smf[NETW + oj];
        float dn = nets;
        for (int i = 0; i < 32; i++) {
            int oi = s_ord[i];
            float A = fmaxf(__shfl_sync(0xffffffffu, nets, i), 0.f);
            float needed = -dn;
            float pf = smf[PFW + oi * 32 + oj];
            float cap = (needed > 0.f) ? fminf(needed, pf) : 0.f;
            float C = cap;
#pragma unroll
            for (int o = 1; o < 32; o <<= 1) {
                float x = __shfl_up_sync(0xffffffffu, C, o);
                if (lane >= o) C += x;
            }
            float Cprev = C - cap;
            float avail = A - Cprev;
            bool act = (avail > 0.f) && (needed > 0.f);
            float f = act ? fminf(fminf(avail, needed), pf) : 0.f;
            dn += f * smf[EFFW + oi * 32 + oj];
            smf[FLOWW + i * 32 + lane] = f;
            unsigned ab = __ballot_sync(0xffffffffu, act);
            if (lane == 0) s_actb[i] = ab;
        }
        smf[DNETW + lane] = dn;
        smf[NSRTW + lane] = nets;
    }
    __syncthreads();

    // ================= I. scatter (16 warps x 2 rows) ======================
    {
        float* out_sh = out;
        float* out_ef = out + MATSZ;
        float* out_sent = out + 2 * MATSZ + 1;
        float* out_recv = out_sent + NB;
        float* out_na = out_recv + NB;
        int oj = s_ord[lane];
        int gj = s_gidx[oj];
#pragma unroll
        for (int rr = 0; rr < 2; rr++) {
            int srow = w * 2 + rr;
            int oi = s_ord[srow];
            int gi = s_gidx[oi];
            float f = smf[FLOWW + srow * 32 + lane];
            unsigned ab = s_actb[srow];
            if ((ab >> lane) & 1u) {
                out_sh[(size_t)gi * NB + gj] = f;
                out_ef[(size_t)gi * NB + gj] = smf[EFFW + oi * 32 + oj];
            }
            float v = f;
#pragma unroll
            for (int o = 16; o > 0; o >>= 1) v += __shfl_xor_sync(0xffffffffu, v, o);
            if (lane == 0) {
                out_sent[gi] = v;
                float dnl = smf[DNETW + srow];
                out_recv[gi] = dnl - smf[NSRTW + srow];
                out_na[gi] = dnl;
                smf[RSENTW + srow] = v;
            }
        }
    }
    __syncthreads();

    // ================= J. per-cluster total + last-block global sum ========
    if (t == 0) {
        float tot = 0.f;
#pragma unroll
        for (int i = 0; i < 32; i++) tot += smf[RSENTW + i];
        d_partial[c] = tot;
        __threadfence();
        unsigned old = atomicAdd(&d_ticket, 1u);
        if (old == NC - 1) {
            __threadfence();
            float s0 = 0.f, s1 = 0.f, s2 = 0.f, s3 = 0.f;
#pragma unroll 8
            for (int q = 0; q < NC; q += 4) {
                s0 += __ldcg(d_partial + q);
                s1 += __ldcg(d_partial + q + 1);
                s2 += __ldcg(d_partial + q + 2);
                s3 += __ldcg(d_partial + q + 3);
            }
            out[2 * MATSZ] = (s0 + s1) + (s2 + s3);
            d_ticket = 0;
        }
    }
}

// ------------------------------------------------------------------------------
extern "C" void kernel_launch(void* const* d_in, const int* in_sizes, int n_in,
                              void* d_out, int out_size) {
    const float* emb   = (const float*)d_in[0];
    const float* gen   = (const float*)d_in[1];
    const float* cons  = (const float*)d_in[2];
    const float* pos   = (const float*)d_in[3];
    const float* fpw1  = (const float*)d_in[4];
    const float* fpb1  = (const float*)d_in[5];
    const float* fpw2  = (const float*)d_in[6];
    const float* fpb2  = (const float*)d_in[7];
    const float* fpw3  = (const float*)d_in[8];
    const float* fpb3  = (const float*)d_in[9];
    const float* enw1  = (const float*)d_in[10];
    const float* enb1  = (const float*)d_in[11];
    const float* enw2  = (const float*)d_in[12];
    const float* enb2  = (const float*)d_in[13];
    const float* psw1  = (const float*)d_in[14];
    const float* psb1  = (const float*)d_in[15];
    const float* psw2  = (const float*)d_in[16];
    const float* psb2  = (const float*)d_in[17];
    const int*   assign = (const int*)d_in[18];
    const int*   hour   = (n_in >= 21) ? (const int*)d_in[20] : nullptr;
    float* out = (float*)d_out;

    cudaFuncSetAttribute(mega_kernel,
                         cudaFuncAttributeMaxDynamicSharedMemorySize, SM_BYTES);

    mega_kernel<<<NC, NT, SM_BYTES>>>(emb, gen, cons, pos,
                                      fpw1, fpb1, fpw2, fpb2, fpw3, fpb3,
                                      enw1, enb1, enw2, enb2,
                                      psw1, psb1, psw2, psb2,
                                      assign, hour, out);
}

// round 12
// speedup vs baseline: 2.3518x; 1.0851x over previous
#include <cuda_runtime.h>
#include <math.h>
#include <stdint.h>

#define NB 4096
#define NC 128
#define KC 32
#define MATSZ 16777216ULL   // 4096*4096
#define NT 512

__device__ float d_partial[NC];
__device__ unsigned d_ticket;   // zero-init; last block resets

typedef unsigned long long u64;

__device__ __forceinline__ u64 fma2(u64 a, u64 b, u64 c) {
    u64 d;
    asm("fma.rn.f32x2 %0, %1, %2, %3;" : "=l"(d) : "l"(a), "l"(b), "l"(c));
    return d;
}
#define PK2(v, lo, hi)   asm("mov.b64 %0, {%1, %2};" : "=l"(v) : "f"(lo), "f"(hi))
#define UNPK2(lo, hi, v) asm("mov.b64 {%0, %1}, %2;" : "=f"(lo), "=f"(hi) : "l"(v))

__device__ __forceinline__ uint32_t f2tf(float f) {
    uint32_t r;
    asm("cvt.rna.tf32.f32 %0, %1;" : "=r"(r) : "f"(f));
    return r;
}
#define MMA_TF32(d0, d1, d2, d3, a0, a1, a2, a3, b0, b1) \
    asm volatile("mma.sync.aligned.m16n8k8.row.col.f32.tf32.tf32.f32 " \
                 "{%0,%1,%2,%3}, {%4,%5,%6,%7}, {%8,%9}, {%0,%1,%2,%3};" \
                 : "+f"(d0), "+f"(d1), "+f"(d2), "+f"(d3) \
                 : "r"(a0), "r"(a1), "r"(a2), "r"(a3), "r"(b0), "r"(b1))

#define BSYNC256(id) asm volatile("bar.sync %0, %1;" :: "n"(id), "n"(256) : "memory")

// ---- dynamic smem word offsets -------------------------------------------
#define SCRATCH 0       // 8448 w: emb rows (stride 129) -> w1 staging (stride 260)
#define EMBT   8448     // 4224 w  embT[k*33 + r]
#define PST    12672    // 4224 w  psw1T[e*33 + m]
#define W2FRAG 16896    // 8192 w: B fragments [(tp*8+nt)*32+lane] uint4
#define HIT    25088    // 4224 w  hiT[k*33 + i]
#define HJT    29312    // 4224 w  hjT[k*33 + j]  (cv merged at store)
#define DISTW  33536    // 1024
#define EFFW   34560    // 1024
#define PFW    35584    // 1024
#define FLOWW  36608    // 1024
#define W1DW   37632    // 128
#define CVW    37760    // 128
#define B2FW   37888    // 64
#define W3FW   37952    // 64
#define GIDX   38016    // int[32]
#define NETW   38048
#define PRIOW  38080
#define ORDW   38112
#define ACTBW  38144
#define DNETW  38176
#define NSRTW  38208
#define RSENTW 38240
#define WCNTW  38272    // int[16]
#define POSW   38288    // float2[32] = 64 w (8B aligned)
#define SM_WORDS 38360
#define SM_BYTES (SM_WORDS * 4)
#define W1STRIDE 260

__global__ void __launch_bounds__(NT, 1) mega_kernel(
    const float* __restrict__ emb,  const float* __restrict__ gen,
    const float* __restrict__ cons, const float* __restrict__ pos,
    const float* __restrict__ fpw1, const float* __restrict__ fpb1,
    const float* __restrict__ fpw2, const float* __restrict__ fpb2,
    const float* __restrict__ fpw3, const float* __restrict__ fpb3,
    const float* __restrict__ enw1, const float* __restrict__ enb1,
    const float* __restrict__ enw2, const float* __restrict__ enb2,
    const float* __restrict__ psw1, const float* __restrict__ psb1,
    const float* __restrict__ psw2, const float* __restrict__ psb2,
    const int* __restrict__ assign, const int* __restrict__ hour_p,
    float* __restrict__ out) {
    extern __shared__ float smf[];
    int* s_gidx = (int*)(smf + GIDX);
    int* s_ord  = (int*)(smf + ORDW);
    unsigned* s_actb = (unsigned*)(smf + ACTBW);
    int* s_wcnt = (int*)(smf + WCNTW);
    float2* s_pos2 = (float2*)(smf + POSW);

    const int c = blockIdx.x;
    const int t = threadIdx.x;
    const int w = t >> 5, lane = t & 31;
    const int hour = hour_p ? *hour_p : 12;

    // ================= A. stable grouping (16 warps, 2-pass ballot) ========
    {
        int a[8];
        const int* ap = assign + w * 256;
#pragma unroll
        for (int q = 0; q < 8; q++) a[q] = ap[q * 32 + lane];
        unsigned balls[8];
        int cnt = 0;
#pragma unroll
        for (int q = 0; q < 8; q++) {
            balls[q] = __ballot_sync(0xffffffffu, a[q] == c);
            cnt += __popc(balls[q]);
        }
        if (lane == 0) s_wcnt[w] = cnt;
        __syncthreads();
        int run = 0;
        for (int ww = 0; ww < 16; ww++) if (ww < w) run += s_wcnt[ww];
#pragma unroll
        for (int q = 0; q < 8; q++) {
            if (a[q] == c) {
                int p = run + __popc(balls[q] & ((1u << lane) - 1u));
                if (p < KC) s_gidx[p] = w * 256 + q * 32 + lane;
            }
            run += __popc(balls[q]);
        }
    }
    __syncthreads();

    // ================= B. net, positions, cv/w1d/b2/w3, emb stage ==========
    if (t < KC) {
        int b = s_gidx[t];
        smf[NETW + t] = gen[b * 24 + hour] - cons[b * 24 + hour];
        s_pos2[t] = make_float2(pos[b * 2], pos[b * 2 + 1]);
    }
    {
        float hour_f = (float)hour * (1.f / 24.f);
        if (t >= 256 && t < 384) {
            int k = t - 256;
            smf[W1DW + k] = fpw1[(size_t)k * 258 + 256];
            smf[CVW + k] = fmaf(hour_f, fpw1[(size_t)k * 258 + 257], fpb1[k]);
        }
        if (t >= 384 && t < 448) {
            int n = t - 384;
            smf[B2FW + n] = fpb2[n];
            smf[W3FW + n] = fpw3[n];
        }
        for (int i = t; i < 4096; i += NT) {
            int r = i >> 7, k = i & 127;
            smf[SCRATCH + r * 129 + k] = emb[(size_t)s_gidx[r] * 128 + k];
        }
    }
    __syncthreads();
    for (int i = t; i < 4096; i += NT) {
        int k = i >> 5, r = i & 31;
        smf[EMBT + k * 33 + r] = smf[SCRATCH + r * 129 + k];
    }
    __syncthreads();

    // ================= C. forked prologue ==================================
    if (w < 8) {
        // ---- warps 0-7: hij GEMM (lane=row, warp covers 32 out-cols) ------
        u64 acc[16];
#pragma unroll
        for (int u = 0; u < 16; u++) acc[u] = 0ull;
        for (int kc = 0; kc < 4; kc++) {
            BSYNC256(5);
#pragma unroll
            for (int q = 0; q < 32; q++) {
                int cc = q * 8 + w;        // out column 0..255
                float v = (cc < 128)
                    ? fpw1[(size_t)cc * 258 + kc * 32 + lane]
                    : fpw1[(size_t)(cc - 128) * 258 + 128 + kc * 32 + lane];
                smf[SCRATCH + lane * W1STRIDE + cc] = v;
            }
            BSYNC256(5);
            const u64* w1u = (const u64*)(smf + SCRATCH);
#pragma unroll 4
            for (int kk = 0; kk < 32; kk++) {
                int k = kc * 32 + kk;
                float e = smf[EMBT + k * 33 + lane];
                u64 e2; PK2(e2, e, e);
                const ulonglong2* wr =
                    (const ulonglong2*)(w1u + kk * (W1STRIDE / 2) + w * 16);
#pragma unroll
                for (int h = 0; h < 8; h++) {
                    ulonglong2 qq = wr[h];
                    acc[2 * h]     = fma2(e2, qq.x, acc[2 * h]);
                    acc[2 * h + 1] = fma2(e2, qq.y, acc[2 * h + 1]);
                }
            }
        }
#pragma unroll
        for (int u = 0; u < 16; u++) {
            int pc = w * 16 + u;           // out-col pair (2pc, 2pc+1)
            float lo, hi;
            UNPK2(lo, hi, acc[u]);
            if (pc < 64) {
                smf[HIT + (2 * pc) * 33 + lane] = lo;
                smf[HIT + (2 * pc + 1) * 33 + lane] = hi;
            } else {
                int k = 2 * pc - 128;
                smf[HJT + k * 33 + lane] = lo + smf[CVW + k];
                smf[HJT + (k + 1) * 33 + lane] = hi + smf[CVW + k + 1];
            }
        }
    } else {
        // ---- warps 8-15: prio + dist/eff + w2 fragments -------------------
        const int t2 = t - 256;            // 0..255
        for (int i = t2; i < 4096; i += 256) {
            int m = i >> 7, e = i & 127;
            smf[PST + e * 33 + m] = psw1[i];
        }
        BSYNC256(6);
        {
            float b1m = psb1[lane], w2m = psw2[lane], b2s = psb2[0];
#pragma unroll
            for (int rr = 0; rr < 4; rr++) {
                int r = (w - 8) * 4 + rr;
                float acc = b1m;
#pragma unroll 8
                for (int e = 0; e < 128; e++)
                    acc = fmaf(smf[EMBT + e * 33 + r], smf[PST + e * 33 + lane], acc);
                float v = fmaxf(acc, 0.f) * w2m;
#pragma unroll
                for (int o = 16; o > 0; o >>= 1)
                    v += __shfl_xor_sync(0xffffffffu, v, o);
                if (lane == 0) smf[PRIOW + r] = 1.f / (1.f + expf(-(v + b2s)));
            }
        }
        {
            float b2v = enb2[0];
            for (int pp = t2; pp < 1024; pp += 256) {
                int i = pp >> 5, j = pp & 31;
                float2 pi = s_pos2[i], pj = s_pos2[j];
                float dx = pi.x - pj.x, dy = pi.y - pj.y;
                float dist = sqrtf(dx * dx + dy * dy);
                float tq = dist * (1.f / 1000.f);
                float s = 0.f;
#pragma unroll
                for (int l = 0; l < 16; l++)
                    s = fmaf(fmaxf(fmaf(tq, __ldg(enw1 + l), __ldg(enb1 + l)), 0.f),
                             __ldg(enw2 + l), s);
                smf[EFFW + pp] = 0.85f + 0.13f / (1.f + expf(-(s + b2v)));
                smf[DISTW + pp] = dist;
            }
        }
        {
            uint4* bf = (uint4*)(smf + W2FRAG);
            for (int idx = t2; idx < 2048; idx += 256) {
                int tp = idx >> 8;
                int rem = idx & 255;
                int nt = rem >> 5, l2 = rem & 31;
                int n = nt * 8 + (l2 >> 2);
                int kb = tp * 16 + (l2 & 3);
                const float* wrow = fpw2 + n * 128 + kb;
                uint4 v;
                v.x = f2tf(__ldg(wrow));
                v.y = f2tf(__ldg(wrow + 4));
                v.z = f2tf(__ldg(wrow + 8));
                v.w = f2tf(__ldg(wrow + 12));
                bf[idx] = v;
            }
        }
    }
    float b3 = fpb3[0];
    __syncthreads();

    // ================= D. barrier-free mainloop ============================
    if (w < 8) {
        // ---- GEMM warps: inline-A tf32 mma, 16-row strip x 64 n -----------
        const int g = lane >> 2, l4 = lane & 3;
        const int sid = w >> 1;
        const int jl = (w & 1) * 16 + g;
        const int jh = jl + 8;
        const uint4* bfrag = (const uint4*)(smf + W2FRAG);

        for (int it = 0; it < 8; it++) {
            const int isend = 4 * it + sid;
            float ddl = smf[DISTW + isend * 32 + jl];
            float ddh = smf[DISTW + isend * 32 + jh];
            float acc[8][4];
#pragma unroll
            for (int nt = 0; nt < 8; nt++) {
                acc[nt][0] = 0.f; acc[nt][1] = 0.f;
                acc[nt][2] = 0.f; acc[nt][3] = 0.f;
            }
#pragma unroll
            for (int tp = 0; tp < 8; tp++) {
                int kb = tp * 16 + l4;
                float w0 = smf[W1DW + kb],      w1v = smf[W1DW + kb + 4];
                float w2v = smf[W1DW + kb + 8], w3v = smf[W1DW + kb + 12];
                float hi0 = smf[HIT + kb * 33 + isend];
                float hi1 = smf[HIT + (kb + 4) * 33 + isend];
                float hi2 = smf[HIT + (kb + 8) * 33 + isend];
                float hi3 = smf[HIT + (kb + 12) * 33 + isend];
                float hl0 = smf[HJT + kb * 33 + jl];
                float hl1 = smf[HJT + (kb + 4) * 33 + jl];
                float hl2 = smf[HJT + (kb + 8) * 33 + jl];
                float hl3 = smf[HJT + (kb + 12) * 33 + jl];
                float hh0 = smf[HJT + kb * 33 + jh];
                float hh1 = smf[HJT + (kb + 4) * 33 + jh];
                float hh2 = smf[HJT + (kb + 8) * 33 + jh];
                float hh3 = smf[HJT + (kb + 12) * 33 + jh];
                uint32_t a0 = f2tf(fmaxf(hi0 + fmaf(ddl, w0, hl0), 0.f));
                uint32_t a1 = f2tf(fmaxf(hi0 + fmaf(ddh, w0, hh0), 0.f));
                uint32_t a2 = f2tf(fmaxf(hi1 + fmaf(ddl, w1v, hl1), 0.f));
                uint32_t a3 = f2tf(fmaxf(hi1 + fmaf(ddh, w1v, hh1), 0.f));
                uint32_t a4 = f2tf(fmaxf(hi2 + fmaf(ddl, w2v, hl2), 0.f));
                uint32_t a5 = f2tf(fmaxf(hi2 + fmaf(ddh, w2v, hh2), 0.f));
                uint32_t a6 = f2tf(fmaxf(hi3 + fmaf(ddl, w3v, hl3), 0.f));
                uint32_t a7 = f2tf(fmaxf(hi3 + fmaf(ddh, w3v, hh3), 0.f));
                const uint4* bp = bfrag + tp * 256 + lane;
#pragma unroll
                for (int nt = 0; nt < 8; nt++) {
                    uint4 bv = bp[nt * 32];
                    MMA_TF32(acc[nt][0], acc[nt][1], acc[nt][2], acc[nt][3],
                             a0, a1, a2, a3, bv.x, bv.y);
                    MMA_TF32(acc[nt][0], acc[nt][1], acc[nt][2], acc[nt][3],
                             a4, a5, a6, a7, bv.z, bv.w);
                }
            }
            // epilogue: relu(+b2) dot w3 over 64 n, quad reduce, softplus
            float vlo = 0.f, vhi = 0.f;
#pragma unroll
            for (int nt = 0; nt < 8; nt++) {
                int n0 = nt * 8 + 2 * l4;
                float b2a = smf[B2FW + n0], b2b = smf[B2FW + n0 + 1];
                float w3a = smf[W3FW + n0], w3b = smf[W3FW + n0 + 1];
                vlo = fmaf(fmaxf(acc[nt][0] + b2a, 0.f), w3a, vlo);
                vlo = fmaf(fmaxf(acc[nt][1] + b2b, 0.f), w3b, vlo);
                vhi = fmaf(fmaxf(acc[nt][2] + b2a, 0.f), w3a, vhi);
                vhi = fmaf(fmaxf(acc[nt][3] + b2b, 0.f), w3b, vhi);
            }
            vlo += __shfl_xor_sync(0xffffffffu, vlo, 1);
            vlo += __shfl_xor_sync(0xffffffffu, vlo, 2);
            vhi += __shfl_xor_sync(0xffffffffu, vhi, 1);
            vhi += __shfl_xor_sync(0xffffffffu, vhi, 2);
            if (l4 == 0) {
                float x = vlo + b3;
                smf[PFW + isend * 32 + jl] = (x > 20.f) ? x : log1pf(expf(x));
                x = vhi + b3;
                smf[PFW + isend * 32 + jh] = (x > 20.f) ? x : log1pf(expf(x));
            }
        }
    } else {
        // ---- fill warps: stream all default output rows -------------------
        const int ft = t - 256;            // 0..255
        const float4 z4 = make_float4(0.f, 0.f, 0.f, 0.f);
        const float4 o4 = make_float4(1.f, 1.f, 1.f, 1.f);
        float4* outS4 = (float4*)out;
        float4* outE4 = (float4*)(out + MATSZ);
#pragma unroll 4
        for (int r = 0; r < 32; r++) {
            size_t rb = (size_t)s_gidx[r] * 1024;
#pragma unroll
            for (int q = 0; q < 4; q++) {
                outS4[rb + q * 256 + ft] = z4;
                outE4[rb + q * 256 + ft] = o4;
            }
        }
    }
    __syncthreads();

    // ================= E. greedy (warp 0, prefix-scan water-filling) =======
    if (w == 0) {
        float pr = smf[PRIOW + lane];
        int r = 0;
#pragma unroll
        for (int l = 0; l < KC; l++) {
            float q = smf[PRIOW + l];
            r += (q > pr) || (q == pr && l < lane);
        }
        s_ord[r] = lane;
        __syncwarp();
        int oj = s_ord[lane];
        float nets = smf[NETW + oj];
        float dn = nets;
        for (int i = 0; i < 32; i++) {
            int oi = s_ord[i];
            float A = fmaxf(__shfl_sync(0xffffffffu, nets, i), 0.f);
            float needed = -dn;
            float pf = smf[PFW + oi * 32 + oj];
            float cap = (needed > 0.f) ? fminf(needed, pf) : 0.f;
            float C = cap;
#pragma unroll
            for (int o = 1; o < 32; o <<= 1) {
                float x = __shfl_up_sync(0xffffffffu, C, o);
                if (lane >= o) C += x;
            }
            float Cprev = C - cap;
            float avail = A - Cprev;
            bool act = (avail > 0.f) && (needed > 0.f);
            float f = act ? fminf(fminf(avail, needed), pf) : 0.f;
            dn += f * smf[EFFW + oi * 32 + oj];
            smf[FLOWW + i * 32 + lane] = f;
            unsigned ab = __ballot_sync(0xffffffffu, act);
            if (lane == 0) s_actb[i] = ab;
        }
        smf[DNETW + lane] = dn;
        smf[NSRTW + lane] = nets;
    }
    __syncthreads();

    // ================= F. scatter (16 warps x 2 rows) ======================
    {
        float* out_sh = out;
        float* out_ef = out + MATSZ;
        float* out_sent = out + 2 * MATSZ + 1;
        float* out_recv = out_sent + NB;
        float* out_na = out_recv + NB;
        int oj = s_ord[lane];
        int gj = s_gidx[oj];
#pragma unroll
        for (int rr = 0; rr < 2; rr++) {
            int srow = w * 2 + rr;
            int oi = s_ord[srow];
            int gi = s_gidx[oi];
            float f = smf[FLOWW + srow * 32 + lane];
            unsigned ab = s_actb[srow];
            if ((ab >> lane) & 1u) {
                out_sh[(size_t)gi * NB + gj] = f;
                out_ef[(size_t)gi * NB + gj] = smf[EFFW + oi * 32 + oj];
            }
            float v = f;
#pragma unroll
            for (int o = 16; o > 0; o >>= 1) v += __shfl_xor_sync(0xffffffffu, v, o);
            if (lane == 0) {
                out_sent[gi] = v;
                float dnl = smf[DNETW + srow];
                out_recv[gi] = dnl - smf[NSRTW + srow];
                out_na[gi] = dnl;
                smf[RSENTW + srow] = v;
            }
        }
    }
    __syncthreads();

    // ================= G. per-cluster total + last-block global sum ========
    if (t == 0) {
        float tot = 0.f;
#pragma unroll
        for (int i = 0; i < 32; i++) tot += smf[RSENTW + i];
        d_partial[c] = tot;
        __threadfence();
        unsigned old = atomicAdd(&d_ticket, 1u);
        if (old == NC - 1) {
            __threadfence();
            float s0 = 0.f, s1 = 0.f, s2 = 0.f, s3 = 0.f;
#pragma unroll 8
            for (int q = 0; q < NC; q += 4) {
                s0 += __ldcg(d_partial + q);
                s1 += __ldcg(d_partial + q + 1);
                s2 += __ldcg(d_partial + q + 2);
                s3 += __ldcg(d_partial + q + 3);
            }
            out[2 * MATSZ] = (s0 + s1) + (s2 + s3);
            d_ticket = 0;
        }
    }
}

// ------------------------------------------------------------------------------
extern "C" void kernel_launch(void* const* d_in, const int* in_sizes, int n_in,
                              void* d_out, int out_size) {
    const float* emb   = (const float*)d_in[0];
    const float* gen   = (const float*)d_in[1];
    const float* cons  = (const float*)d_in[2];
    const float* pos   = (const float*)d_in[3];
    const float* fpw1  = (const float*)d_in[4];
    const float* fpb1  = (const float*)d_in[5];
    const float* fpw2  = (const float*)d_in[6];
    const float* fpb2  = (const float*)d_in[7];
    const float* fpw3  = (const float*)d_in[8];
    const float* fpb3  = (const float*)d_in[9];
    const float* enw1  = (const float*)d_in[10];
    const float* enb1  = (const float*)d_in[11];
    const float* enw2  = (const float*)d_in[12];
    const float* enb2  = (const float*)d_in[13];
    const float* psw1  = (const float*)d_in[14];
    const float* psb1  = (const float*)d_in[15];
    const float* psw2  = (const float*)d_in[16];
    const float* psb2  = (const float*)d_in[17];
    const int*   assign = (const int*)d_in[18];
    const int*   hour   = (n_in >= 21) ? (const int*)d_in[20] : nullptr;
    float* out = (float*)d_out;

    cudaFuncSetAttribute(mega_kernel,
                         cudaFuncAttributeMaxDynamicSharedMemorySize, SM_BYTES);

    mega_kernel<<<NC, NT, SM_BYTES>>>(emb, gen, cons, pos,
                                      fpw1, fpb1, fpw2, fpb2, fpw3, fpb3,
                                      enw1, enb1, enw2, enb2,
                                      psw1, psb1, psw2, psb2,
                                      assign, hour, out);
}